// round 1
// baseline (speedup 1.0000x reference)
#include <cuda_runtime.h>
#include <cstdint>

#define N_NODES 100000
#define N_EDGES 3200000
#define F_IN 128
#define H 128
#define HQ 256
#define A_DIM 10

static inline int cdiv(int a, int b) { return (a + b - 1) / b; }

// ---------------- scratch (device globals; no allocation allowed) ----------------
__device__ float g_h1[(size_t)N_NODES * H];     // relu(x@W_enc+b_enc)
__device__ float g_xw[(size_t)N_NODES * H];     // h1@W_gcn
__device__ float g_h2[(size_t)N_NODES * H];     // relu(gcn agg)
__device__ float g_t[(size_t)N_NODES * HQ];     // relu(h2@W1+b1)
__device__ float g_dinv[N_NODES];
__device__ int   g_deg[N_NODES];
__device__ int   g_rowptr[N_NODES + 1];
__device__ int   g_cursor[N_NODES];
__device__ int   g_csrc[N_EDGES];
__device__ int   g_ei32[2 * N_EDGES];
__device__ int   g_is32;

// ---------------- edge dtype detection + conversion ----------------
__global__ void k_detect(const void* ei) {
    if (threadIdx.x == 0 && blockIdx.x == 0) {
        const long long* p = (const long long*)ei;
        int is32 = 0;
        for (int i = 0; i < 64; i++) {
            long long v = p[i];
            if (v < 0 || v >= (long long)N_NODES) { is32 = 1; break; }
        }
        g_is32 = is32;
    }
}

__global__ void k_cvt(const void* ei) {
    int i = blockIdx.x * blockDim.x + threadIdx.x;
    if (i >= 2 * N_EDGES) return;
    int v;
    if (g_is32) v = ((const int*)ei)[i];
    else        v = (int)((const long long*)ei)[i];
    g_ei32[i] = v;
}

__global__ void k_zero_deg() {
    int i = blockIdx.x * blockDim.x + threadIdx.x;
    if (i < N_NODES) g_deg[i] = 0;
}

__global__ void k_hist() {
    int i = blockIdx.x * blockDim.x + threadIdx.x;
    if (i >= N_EDGES) return;
    atomicAdd(&g_deg[g_ei32[N_EDGES + i]], 1);
}

// single-block exclusive scan of deg -> rowptr (+cursor copy, dinv)
__global__ void k_scan() {
    __shared__ int warpsum[32];
    __shared__ int s_carry;
    int tid = threadIdx.x, lane = tid & 31, wid = tid >> 5;
    if (tid == 0) s_carry = 0;
    __syncthreads();
    for (int base = 0; base < N_NODES; base += 1024) {
        int i = base + tid;
        int v = (i < N_NODES) ? g_deg[i] : 0;
        int x = v;
#pragma unroll
        for (int off = 1; off < 32; off <<= 1) {
            int y = __shfl_up_sync(0xffffffffu, x, off);
            if (lane >= off) x += y;
        }
        if (lane == 31) warpsum[wid] = x;
        __syncthreads();
        if (wid == 0) {
            int w = warpsum[lane];
#pragma unroll
            for (int off = 1; off < 32; off <<= 1) {
                int y = __shfl_up_sync(0xffffffffu, w, off);
                if (lane >= off) w += y;
            }
            warpsum[lane] = w;
        }
        __syncthreads();
        int wpre = (wid > 0) ? warpsum[wid - 1] : 0;
        int incl = x + wpre;
        int excl = incl - v;
        int carry = s_carry;
        if (i < N_NODES) {
            int rp = carry + excl;
            g_rowptr[i] = rp;
            g_cursor[i] = rp;
            g_dinv[i] = rsqrtf((float)(v + 1));
        }
        __syncthreads();
        if (tid == 1023) s_carry = carry + incl;
        __syncthreads();
    }
    if (threadIdx.x == 0) g_rowptr[N_NODES] = s_carry;
}

__global__ void k_fill() {
    int i = blockIdx.x * blockDim.x + threadIdx.x;
    if (i >= N_EDGES) return;
    int s = g_ei32[i];
    int d = g_ei32[N_EDGES + i];
    int p = atomicAdd(&g_cursor[d], 1);
    g_csrc[p] = s;
}

// ---------------- fp32 SGEMM: C = [relu](A[M,K=128] @ B[K,N] + bias) ----------------
// BM=128, BN=128, BK=32, 256 threads, 8x8 per-thread tile.
template <bool RELU, bool BIAS>
__global__ __launch_bounds__(256) void sgemm_kernel(
    const float* __restrict__ A, const float* __restrict__ B,
    const float* __restrict__ bias, float* __restrict__ C,
    int M, int ldb, int ldc)
{
    __shared__ float As[32][132];
    __shared__ float Bs[32][132];

    const int tid = threadIdx.x;
    const int tx = tid & 15;        // 0..15 -> 8 cols each
    const int ty = tid >> 4;        // 0..15 -> 8 rows each
    const int rowBase = blockIdx.x * 128;
    const int colBase = blockIdx.y * 128;

    float acc[8][8];
#pragma unroll
    for (int i = 0; i < 8; i++)
#pragma unroll
        for (int j = 0; j < 8; j++) acc[i][j] = 0.f;

    for (int kt = 0; kt < 128; kt += 32) {
        // load A tile (transposed into As[k][row]) and B tile
#pragma unroll
        for (int t = 0; t < 4; t++) {
            int slot = tid + t * 256;
            {   // A: 128 rows x 32 cols
                int r  = slot >> 3;
                int c4 = (slot & 7) * 4;
                int gr = rowBase + r;
                float4 v = make_float4(0.f, 0.f, 0.f, 0.f);
                if (gr < M) v = *(const float4*)&A[(size_t)gr * 128 + kt + c4];
                As[c4 + 0][r] = v.x;
                As[c4 + 1][r] = v.y;
                As[c4 + 2][r] = v.z;
                As[c4 + 3][r] = v.w;
            }
            {   // B: 32 rows x 128 cols
                int k  = slot >> 5;
                int c4 = (slot & 31) * 4;
                float4 v = *(const float4*)&B[(size_t)(kt + k) * ldb + colBase + c4];
                *(float4*)&Bs[k][c4] = v;
            }
        }
        __syncthreads();

#pragma unroll
        for (int k = 0; k < 32; k++) {
            float4 a0 = *(const float4*)&As[k][ty * 8];
            float4 a1 = *(const float4*)&As[k][ty * 8 + 4];
            float4 b0 = *(const float4*)&Bs[k][tx * 8];
            float4 b1 = *(const float4*)&Bs[k][tx * 8 + 4];
            float ar[8] = {a0.x, a0.y, a0.z, a0.w, a1.x, a1.y, a1.z, a1.w};
            float br[8] = {b0.x, b0.y, b0.z, b0.w, b1.x, b1.y, b1.z, b1.w};
#pragma unroll
            for (int i = 0; i < 8; i++)
#pragma unroll
                for (int j = 0; j < 8; j++)
                    acc[i][j] = fmaf(ar[i], br[j], acc[i][j]);
        }
        __syncthreads();
    }

    // epilogue
    float bv[8];
#pragma unroll
    for (int j = 0; j < 8; j++)
        bv[j] = BIAS ? bias[colBase + tx * 8 + j] : 0.f;

#pragma unroll
    for (int i = 0; i < 8; i++) {
        int row = rowBase + ty * 8 + i;
        if (row >= M) continue;
        float out[8];
#pragma unroll
        for (int j = 0; j < 8; j++) {
            float v = acc[i][j] + bv[j];
            out[j] = RELU ? fmaxf(v, 0.f) : v;
        }
        *(float4*)&C[(size_t)row * ldc + colBase + tx * 8]     = make_float4(out[0], out[1], out[2], out[3]);
        *(float4*)&C[(size_t)row * ldc + colBase + tx * 8 + 4] = make_float4(out[4], out[5], out[6], out[7]);
    }
}

// ---------------- GCN aggregation: warp per node, gather only ----------------
__global__ void k_agg(const float* __restrict__ b_gcn) {
    int gw = (blockIdx.x * blockDim.x + threadIdx.x) >> 5;
    int lane = threadIdx.x & 31;
    if (gw >= N_NODES) return;

    int beg = g_rowptr[gw];
    int end = g_rowptr[gw + 1];

    float4 acc = make_float4(0.f, 0.f, 0.f, 0.f);
    for (int base = beg; base < end; base += 32) {
        int e = base + lane;
        int s = (e < end) ? g_csrc[e] : 0;
        int cnt = min(32, end - base);
        for (int j = 0; j < cnt; j++) {
            int sj = __shfl_sync(0xffffffffu, s, j);
            float c = g_dinv[sj];
            float4 v = *(const float4*)&g_xw[(size_t)sj * H + lane * 4];
            acc.x = fmaf(c, v.x, acc.x);
            acc.y = fmaf(c, v.y, acc.y);
            acc.z = fmaf(c, v.z, acc.z);
            acc.w = fmaf(c, v.w, acc.w);
        }
    }

    float di = g_dinv[gw];
    float sc = di * di;
    float4 self = *(const float4*)&g_xw[(size_t)gw * H + lane * 4];
    float4 b    = *(const float4*)&b_gcn[lane * 4];
    float4 o;
    o.x = fmaxf(fmaf(di, acc.x, fmaf(sc, self.x, b.x)), 0.f);
    o.y = fmaxf(fmaf(di, acc.y, fmaf(sc, self.y, b.y)), 0.f);
    o.z = fmaxf(fmaf(di, acc.z, fmaf(sc, self.z, b.z)), 0.f);
    o.w = fmaxf(fmaf(di, acc.w, fmaf(sc, self.w, b.w)), 0.f);
    *(float4*)&g_h2[(size_t)gw * H + lane * 4] = o;
}

// ---------------- final skinny GEMM: out = t @ W2 + b2, warp per row ----------------
__global__ void k_qout(const float* __restrict__ W2, const float* __restrict__ b2,
                       float* __restrict__ out) {
    __shared__ float sW2[HQ * A_DIM];
    int tid = threadIdx.x;
    for (int j = tid; j < HQ * A_DIM; j += blockDim.x) sW2[j] = W2[j];
    __syncthreads();

    int gw = (blockIdx.x * blockDim.x + tid) >> 5;
    int lane = tid & 31;
    if (gw >= N_NODES) return;

    const float* trow = &g_t[(size_t)gw * HQ];
    float4 t0 = *(const float4*)&trow[lane * 4];
    float4 t1 = *(const float4*)&trow[128 + lane * 4];
    int k0 = lane * 4;
    int k1 = 128 + lane * 4;

#pragma unroll
    for (int a = 0; a < A_DIM; a++) {
        float p = t0.x * sW2[(k0 + 0) * A_DIM + a]
                + t0.y * sW2[(k0 + 1) * A_DIM + a]
                + t0.z * sW2[(k0 + 2) * A_DIM + a]
                + t0.w * sW2[(k0 + 3) * A_DIM + a]
                + t1.x * sW2[(k1 + 0) * A_DIM + a]
                + t1.y * sW2[(k1 + 1) * A_DIM + a]
                + t1.z * sW2[(k1 + 2) * A_DIM + a]
                + t1.w * sW2[(k1 + 3) * A_DIM + a];
#pragma unroll
        for (int off = 16; off; off >>= 1) p += __shfl_xor_sync(0xffffffffu, p, off);
        if (lane == 0) out[(size_t)gw * A_DIM + a] = p + b2[a];
    }
}

// ---------------- launcher ----------------
extern "C" void kernel_launch(void* const* d_in, const int* in_sizes, int n_in,
                              void* d_out, int out_size) {
    const float* x     = (const float*)d_in[0];
    const void*  ei    = d_in[1];
    const float* W_enc = (const float*)d_in[2];
    const float* b_enc = (const float*)d_in[3];
    const float* W_gcn = (const float*)d_in[4];
    const float* b_gcn = (const float*)d_in[5];
    const float* W1    = (const float*)d_in[6];
    const float* b1    = (const float*)d_in[7];
    const float* W2    = (const float*)d_in[8];
    const float* b2    = (const float*)d_in[9];
    float* out = (float*)d_out;

    float* h1 = nullptr; float* xw = nullptr; float* h2 = nullptr; float* t = nullptr;
    cudaGetSymbolAddress((void**)&h1, g_h1);
    cudaGetSymbolAddress((void**)&xw, g_xw);
    cudaGetSymbolAddress((void**)&h2, g_h2);
    cudaGetSymbolAddress((void**)&t,  g_t);

    // CSR build
    k_detect<<<1, 32>>>(ei);
    k_zero_deg<<<cdiv(N_NODES, 256), 256>>>();
    k_cvt<<<cdiv(2 * N_EDGES, 256), 256>>>(ei);
    k_hist<<<cdiv(N_EDGES, 256), 256>>>();
    k_scan<<<1, 1024>>>();
    k_fill<<<cdiv(N_EDGES, 256), 256>>>();

    // encoder: h1 = relu(x @ W_enc + b_enc)
    sgemm_kernel<true, true><<<dim3(cdiv(N_NODES, 128), 1), 256>>>(
        x, W_enc, b_enc, h1, N_NODES, H, H);
    // xw = h1 @ W_gcn
    sgemm_kernel<false, false><<<dim3(cdiv(N_NODES, 128), 1), 256>>>(
        h1, W_gcn, nullptr, xw, N_NODES, H, H);
    // gcn aggregation + bias + relu -> h2
    k_agg<<<cdiv(N_NODES * 32, 256), 256>>>(b_gcn);
    // t = relu(h2 @ W1 + b1)  [N x 256]
    sgemm_kernel<true, true><<<dim3(cdiv(N_NODES, 128), 2), 256>>>(
        h2, W1, b1, t, N_NODES, HQ, HQ);
    // out = t @ W2 + b2
    k_qout<<<cdiv(N_NODES * 32, 256), 256>>>(W2, b2, out);
}

// round 2
// speedup vs baseline: 1.1861x; 1.1861x over previous
#include <cuda_runtime.h>
#include <mma.h>
#include <cstdint>

using namespace nvcuda;

#define N_NODES 100000
#define N_PAD   100096   // 782 * 128, GEMM tile padding for scratch outputs
#define N_EDGES 3200000
#define F_IN 128
#define H 128
#define HQ 256
#define A_DIM 10
#define NBLK_SCAN 98     // cdiv(100000, 1024)

static inline int cdiv(int a, int b) { return (a + b - 1) / b; }

// ---------------- scratch (device globals; no allocation allowed) ----------------
__device__ float g_h1[(size_t)N_PAD * H];     // x@W_enc (raw, no bias/relu)
__device__ float g_xw[(size_t)N_PAD * H];     // relu(h1+b_enc)@W_gcn
__device__ float g_h2[(size_t)N_PAD * H];     // relu(gcn agg)  (rows >= N unused)
__device__ float g_t[(size_t)N_PAD * HQ];     // h2@W1 (raw)
__device__ float g_dinv[N_NODES];
__device__ int   g_deg[N_NODES];
__device__ int   g_rowptr[N_NODES + 1];
__device__ int   g_cursor[N_NODES];
__device__ int   g_csrc[N_EDGES];
__device__ int   g_ei32[2 * N_EDGES];
__device__ int   g_is32;
__device__ int   g_bsum[NBLK_SCAN];
__device__ int   g_boff[NBLK_SCAN];

// ---------------- edge dtype detection + conversion ----------------
__global__ void k_detect(const void* ei) {
    if (threadIdx.x == 0 && blockIdx.x == 0) {
        const long long* p = (const long long*)ei;
        int is32 = 0;
        for (int i = 0; i < 64; i++) {
            long long v = p[i];
            if (v < 0 || v >= (long long)N_NODES) { is32 = 1; break; }
        }
        g_is32 = is32;
    }
}

__global__ void k_cvt(const void* ei) {
    int i = blockIdx.x * blockDim.x + threadIdx.x;
    if (i >= 2 * N_EDGES) return;
    int v;
    if (g_is32) v = ((const int*)ei)[i];
    else        v = (int)((const long long*)ei)[i];
    g_ei32[i] = v;
}

__global__ void k_zero_deg() {
    int i = blockIdx.x * blockDim.x + threadIdx.x;
    if (i < N_NODES) g_deg[i] = 0;
}

__global__ void k_hist() {
    int i = blockIdx.x * blockDim.x + threadIdx.x;
    if (i >= N_EDGES) return;
    atomicAdd(&g_deg[g_ei32[N_EDGES + i]], 1);
}

// ---------- 3-phase scan: deg -> rowptr/cursor (exclusive) + dinv ----------
__global__ void k_scan1() {   // grid NBLK_SCAN x 1024
    __shared__ int warpsum[32];
    int tid = threadIdx.x, lane = tid & 31, wid = tid >> 5;
    int i = blockIdx.x * 1024 + tid;
    int v = (i < N_NODES) ? g_deg[i] : 0;
    int x = v;
#pragma unroll
    for (int off = 1; off < 32; off <<= 1) {
        int y = __shfl_up_sync(0xffffffffu, x, off);
        if (lane >= off) x += y;
    }
    if (lane == 31) warpsum[wid] = x;
    __syncthreads();
    if (wid == 0) {
        int w = warpsum[lane];
#pragma unroll
        for (int off = 1; off < 32; off <<= 1) {
            int y = __shfl_up_sync(0xffffffffu, w, off);
            if (lane >= off) w += y;
        }
        warpsum[lane] = w;
    }
    __syncthreads();
    int incl = x + (wid > 0 ? warpsum[wid - 1] : 0);
    if (i < N_NODES) {
        g_rowptr[i] = incl - v;          // block-local exclusive
        g_dinv[i] = rsqrtf((float)(v + 1));
    }
    if (tid == 1023) g_bsum[blockIdx.x] = incl;
}

__global__ void k_scan2() {   // 1 block, 128 threads
    __shared__ int s[128];
    int t = threadIdx.x;
    s[t] = (t < NBLK_SCAN) ? g_bsum[t] : 0;
    __syncthreads();
    for (int off = 1; off < 128; off <<= 1) {
        int v = (t >= off) ? s[t - off] : 0;
        __syncthreads();
        s[t] += v;
        __syncthreads();
    }
    if (t < NBLK_SCAN) g_boff[t] = (t > 0) ? s[t - 1] : 0;
    if (t == 0) g_rowptr[N_NODES] = s[NBLK_SCAN - 1];
}

__global__ void k_scan3() {   // grid NBLK_SCAN x 1024 (same mapping as scan1)
    int i = blockIdx.x * 1024 + threadIdx.x;
    if (i >= N_NODES) return;
    int r = g_rowptr[i] + g_boff[blockIdx.x];
    g_rowptr[i] = r;
    g_cursor[i] = r;
}

__global__ void k_fill() {
    int i = blockIdx.x * blockDim.x + threadIdx.x;
    if (i >= N_EDGES) return;
    int s = g_ei32[i];
    int d = g_ei32[N_EDGES + i];
    int p = atomicAdd(&g_cursor[d], 1);
    g_csrc[p] = s;
}

// ---------------- tf32 wmma GEMM: C = Atrans(A) @ B ----------------
// A is [M x 128] row-major; optional per-column transform relu(a + abias[k]).
// Block tile 128x128, 8 warps (4m x 2n), warp tile 32x64, frag 16x16x8.
// C rows written unguarded -> C must be padded to multiple of 128 rows.
#define LDA 36
#define LDB 132

template <bool ARELU>
__global__ __launch_bounds__(256) void gemm_tf32(
    const float* __restrict__ A, const float* __restrict__ B,
    const float* __restrict__ abias, float* __restrict__ C,
    int M, int ldb, int ldc)
{
    __shared__ float As[128 * LDA];
    __shared__ float Bs[32 * LDB];

    const int tid = threadIdx.x;
    const int wid = tid >> 5;
    const int warp_m = wid & 3;          // 0..3 -> 32 rows each
    const int warp_n = wid >> 2;         // 0..1 -> 64 cols each
    const int rowBase = blockIdx.x * 128;
    const int colBase = blockIdx.y * 128;

    wmma::fragment<wmma::accumulator, 16, 16, 8, float> acc[2][4];
#pragma unroll
    for (int mt = 0; mt < 2; mt++)
#pragma unroll
        for (int nt = 0; nt < 4; nt++) wmma::fill_fragment(acc[mt][nt], 0.f);

    for (int kt = 0; kt < 128; kt += 32) {
        // A stage: 128 rows x 32 cols
#pragma unroll
        for (int t = 0; t < 4; t++) {
            int slot = tid + t * 256;
            int r = slot >> 3;
            int c4 = (slot & 7) * 4;
            int gr = rowBase + r;
            float4 v = make_float4(0.f, 0.f, 0.f, 0.f);
            if (gr < M) v = *(const float4*)&A[(size_t)gr * 128 + kt + c4];
            if (ARELU) {
                const float4 b = *(const float4*)&abias[kt + c4];
                v.x = fmaxf(v.x + b.x, 0.f);
                v.y = fmaxf(v.y + b.y, 0.f);
                v.z = fmaxf(v.z + b.z, 0.f);
                v.w = fmaxf(v.w + b.w, 0.f);
            }
            *(float4*)&As[r * LDA + c4] = v;
        }
        // B stage: 32 rows x 128 cols
#pragma unroll
        for (int t = 0; t < 4; t++) {
            int slot = tid + t * 256;
            int k = slot >> 5;
            int c4 = (slot & 31) * 4;
            *(float4*)&Bs[k * LDB + c4] =
                *(const float4*)&B[(size_t)(kt + k) * ldb + colBase + c4];
        }
        __syncthreads();

#pragma unroll
        for (int ks = 0; ks < 4; ks++) {
            const int k = ks * 8;
            wmma::fragment<wmma::matrix_a, 16, 16, 8, wmma::precision::tf32, wmma::row_major> af[2];
            wmma::fragment<wmma::matrix_b, 16, 16, 8, wmma::precision::tf32, wmma::row_major> bf[4];
#pragma unroll
            for (int mt = 0; mt < 2; mt++) {
                wmma::load_matrix_sync(af[mt], &As[(warp_m * 32 + mt * 16) * LDA + k], LDA);
#pragma unroll
                for (int e = 0; e < af[mt].num_elements; e++)
                    af[mt].x[e] = wmma::__float_to_tf32(af[mt].x[e]);
            }
#pragma unroll
            for (int nt = 0; nt < 4; nt++) {
                wmma::load_matrix_sync(bf[nt], &Bs[k * LDB + warp_n * 64 + nt * 16], LDB);
#pragma unroll
                for (int e = 0; e < bf[nt].num_elements; e++)
                    bf[nt].x[e] = wmma::__float_to_tf32(bf[nt].x[e]);
            }
#pragma unroll
            for (int mt = 0; mt < 2; mt++)
#pragma unroll
                for (int nt = 0; nt < 4; nt++)
                    wmma::mma_sync(acc[mt][nt], af[mt], bf[nt], acc[mt][nt]);
        }
        __syncthreads();
    }

#pragma unroll
    for (int mt = 0; mt < 2; mt++)
#pragma unroll
        for (int nt = 0; nt < 4; nt++) {
            int row = rowBase + warp_m * 32 + mt * 16;
            int col = colBase + warp_n * 64 + nt * 16;
            wmma::store_matrix_sync(&C[(size_t)row * ldc + col], acc[mt][nt], ldc,
                                    wmma::mem_row_major);
        }
}

// ---------------- GCN aggregation: warp per node, gather only ----------------
__global__ void k_agg(const float* __restrict__ b_gcn) {
    int gw = (blockIdx.x * blockDim.x + threadIdx.x) >> 5;
    int lane = threadIdx.x & 31;
    if (gw >= N_NODES) return;

    int beg = g_rowptr[gw];
    int end = g_rowptr[gw + 1];

    float4 acc = make_float4(0.f, 0.f, 0.f, 0.f);
    for (int base = beg; base < end; base += 32) {
        int e = base + lane;
        int s = (e < end) ? g_csrc[e] : 0;
        int cnt = min(32, end - base);
        for (int j = 0; j < cnt; j++) {
            int sj = __shfl_sync(0xffffffffu, s, j);
            float c = g_dinv[sj];
            float4 v = *(const float4*)&g_xw[(size_t)sj * H + lane * 4];
            acc.x = fmaf(c, v.x, acc.x);
            acc.y = fmaf(c, v.y, acc.y);
            acc.z = fmaf(c, v.z, acc.z);
            acc.w = fmaf(c, v.w, acc.w);
        }
    }

    float di = g_dinv[gw];
    float sc = di * di;
    float4 self = *(const float4*)&g_xw[(size_t)gw * H + lane * 4];
    float4 b    = *(const float4*)&b_gcn[lane * 4];
    float4 o;
    o.x = fmaxf(fmaf(di, acc.x, fmaf(sc, self.x, b.x)), 0.f);
    o.y = fmaxf(fmaf(di, acc.y, fmaf(sc, self.y, b.y)), 0.f);
    o.z = fmaxf(fmaf(di, acc.z, fmaf(sc, self.z, b.z)), 0.f);
    o.w = fmaxf(fmaf(di, acc.w, fmaf(sc, self.w, b.w)), 0.f);
    *(float4*)&g_h2[(size_t)gw * H + lane * 4] = o;
}

// ---------- final skinny GEMM: out = relu(t + b1) @ W2 + b2, warp per row ----------
__global__ void k_qout(const float* __restrict__ W2, const float* __restrict__ b2,
                       const float* __restrict__ b1, float* __restrict__ out) {
    __shared__ float sW2[HQ * A_DIM];
    __shared__ float sb1[HQ];
    int tid = threadIdx.x;
    for (int j = tid; j < HQ * A_DIM; j += blockDim.x) sW2[j] = W2[j];
    for (int j = tid; j < HQ; j += blockDim.x) sb1[j] = b1[j];
    __syncthreads();

    int gw = (blockIdx.x * blockDim.x + tid) >> 5;
    int lane = tid & 31;
    if (gw >= N_NODES) return;

    const float* trow = &g_t[(size_t)gw * HQ];
    float4 t0 = *(const float4*)&trow[lane * 4];
    float4 t1 = *(const float4*)&trow[128 + lane * 4];
    int k0 = lane * 4;
    int k1 = 128 + lane * 4;
    t0.x = fmaxf(t0.x + sb1[k0 + 0], 0.f);
    t0.y = fmaxf(t0.y + sb1[k0 + 1], 0.f);
    t0.z = fmaxf(t0.z + sb1[k0 + 2], 0.f);
    t0.w = fmaxf(t0.w + sb1[k0 + 3], 0.f);
    t1.x = fmaxf(t1.x + sb1[k1 + 0], 0.f);
    t1.y = fmaxf(t1.y + sb1[k1 + 1], 0.f);
    t1.z = fmaxf(t1.z + sb1[k1 + 2], 0.f);
    t1.w = fmaxf(t1.w + sb1[k1 + 3], 0.f);

#pragma unroll
    for (int a = 0; a < A_DIM; a++) {
        float p = t0.x * sW2[(k0 + 0) * A_DIM + a]
                + t0.y * sW2[(k0 + 1) * A_DIM + a]
                + t0.z * sW2[(k0 + 2) * A_DIM + a]
                + t0.w * sW2[(k0 + 3) * A_DIM + a]
                + t1.x * sW2[(k1 + 0) * A_DIM + a]
                + t1.y * sW2[(k1 + 1) * A_DIM + a]
                + t1.z * sW2[(k1 + 2) * A_DIM + a]
                + t1.w * sW2[(k1 + 3) * A_DIM + a];
#pragma unroll
        for (int off = 16; off; off >>= 1) p += __shfl_xor_sync(0xffffffffu, p, off);
        if (lane == 0) out[(size_t)gw * A_DIM + a] = p + b2[a];
    }
}

// ---------------- launcher ----------------
extern "C" void kernel_launch(void* const* d_in, const int* in_sizes, int n_in,
                              void* d_out, int out_size) {
    const float* x     = (const float*)d_in[0];
    const void*  ei    = d_in[1];
    const float* W_enc = (const float*)d_in[2];
    const float* b_enc = (const float*)d_in[3];
    const float* W_gcn = (const float*)d_in[4];
    const float* b_gcn = (const float*)d_in[5];
    const float* W1    = (const float*)d_in[6];
    const float* b1    = (const float*)d_in[7];
    const float* W2    = (const float*)d_in[8];
    const float* b2    = (const float*)d_in[9];
    float* out = (float*)d_out;

    float* h1 = nullptr; float* xw = nullptr; float* h2 = nullptr; float* t = nullptr;
    cudaGetSymbolAddress((void**)&h1, g_h1);
    cudaGetSymbolAddress((void**)&xw, g_xw);
    cudaGetSymbolAddress((void**)&h2, g_h2);
    cudaGetSymbolAddress((void**)&t,  g_t);

    // CSR build
    k_detect<<<1, 32>>>(ei);
    k_zero_deg<<<cdiv(N_NODES, 256), 256>>>();
    k_cvt<<<cdiv(2 * N_EDGES, 256), 256>>>(ei);
    k_hist<<<cdiv(N_EDGES, 256), 256>>>();
    k_scan1<<<NBLK_SCAN, 1024>>>();
    k_scan2<<<1, 128>>>();
    k_scan3<<<NBLK_SCAN, 1024>>>();
    k_fill<<<cdiv(N_EDGES, 256), 256>>>();

    // h1 = x @ W_enc                      (raw)
    gemm_tf32<false><<<dim3(cdiv(N_NODES, 128), 1), 256>>>(
        x, W_enc, nullptr, h1, N_NODES, H, H);
    // xw = relu(h1 + b_enc) @ W_gcn
    gemm_tf32<true><<<dim3(cdiv(N_NODES, 128), 1), 256>>>(
        h1, W_gcn, b_enc, xw, N_NODES, H, H);
    // gcn aggregation + bias + relu -> h2
    k_agg<<<cdiv(N_NODES * 32, 256), 256>>>(b_gcn);
    // t = h2 @ W1                         (raw)
    gemm_tf32<false><<<dim3(cdiv(N_NODES, 128), 2), 256>>>(
        h2, W1, nullptr, t, N_NODES, HQ, HQ);
    // out = relu(t + b1) @ W2 + b2
    k_qout<<<cdiv(N_NODES * 32, 256), 256>>>(W2, b2, b1, out);
}

// round 3
// speedup vs baseline: 1.6083x; 1.3559x over previous
#include <cuda_runtime.h>
#include <mma.h>
#include <cstdint>

using namespace nvcuda;

#define N_NODES 100000
#define N_PAD   100096   // 782 * 128
#define N_EDGES 3200000
#define H 128
#define HQ 256
#define A_DIM 10
#define NBLK_SCAN 98

static inline int cdiv(int a, int b) { return (a + b - 1) / b; }

// ---------------- scratch ----------------
__device__ float g_xw[(size_t)N_PAD * H];     // dinv-scaled relu(x@We+be)@Wg
__device__ float g_h2[(size_t)N_PAD * H];     // relu(gcn agg); rows>=N stay 0
__device__ float g_dinv[N_NODES];
__device__ int   g_deg[N_NODES];
__device__ int   g_rowptr[N_NODES + 1];
__device__ int   g_cursor[N_NODES];
__device__ int   g_csrc[N_EDGES];
__device__ int   g_ei32[2 * N_EDGES];
__device__ int   g_is32;
__device__ int   g_bsum[NBLK_SCAN];
__device__ int   g_boff[NBLK_SCAN];

// ---------------- cp.async helpers ----------------
__device__ __forceinline__ void cp16(void* s, const void* g, bool p) {
    uint32_t sa = (uint32_t)__cvta_generic_to_shared(s);
    int sz = p ? 16 : 0;
    asm volatile("cp.async.cg.shared.global [%0], [%1], 16, %2;\n"
                 :: "r"(sa), "l"(g), "r"(sz));
}
__device__ __forceinline__ void cp_commit() {
    asm volatile("cp.async.commit_group;\n");
}
template <int NN>
__device__ __forceinline__ void cp_wait() {
    asm volatile("cp.async.wait_group %0;\n" :: "n"(NN));
}

// ---------------- edge dtype detect + fused convert/histogram ----------------
__global__ void k_detect(const void* ei) {
    if (threadIdx.x == 0 && blockIdx.x == 0) {
        const long long* p = (const long long*)ei;
        int is32 = 0;
        for (int i = 0; i < 64; i++) {
            long long v = p[i];
            if (v < 0 || v >= (long long)N_NODES) { is32 = 1; break; }
        }
        g_is32 = is32;
    }
}

__global__ void k_zero_deg() {
    int i = blockIdx.x * blockDim.x + threadIdx.x;
    if (i < N_NODES) g_deg[i] = 0;
}

__global__ void k_cvt_hist(const void* ei) {
    int i = blockIdx.x * blockDim.x + threadIdx.x;   // 2 elements per thread
    int base = i * 2;
    if (base >= 2 * N_EDGES) return;
    int v0, v1;
    if (g_is32) {
        int2 p = ((const int2*)ei)[i];
        v0 = p.x; v1 = p.y;
    } else {
        longlong2 p = ((const longlong2*)ei)[i];
        v0 = (int)p.x; v1 = (int)p.y;
    }
    *(int2*)&g_ei32[base] = make_int2(v0, v1);
    if (base >= N_EDGES) {   // dst half
        atomicAdd(&g_deg[v0], 1);
        atomicAdd(&g_deg[v1], 1);
    }
}

// ---------- 3-phase scan ----------
__global__ void k_scan1() {
    __shared__ int warpsum[32];
    int tid = threadIdx.x, lane = tid & 31, wid = tid >> 5;
    int i = blockIdx.x * 1024 + tid;
    int v = (i < N_NODES) ? g_deg[i] : 0;
    int x = v;
#pragma unroll
    for (int off = 1; off < 32; off <<= 1) {
        int y = __shfl_up_sync(0xffffffffu, x, off);
        if (lane >= off) x += y;
    }
    if (lane == 31) warpsum[wid] = x;
    __syncthreads();
    if (wid == 0) {
        int w = warpsum[lane];
#pragma unroll
        for (int off = 1; off < 32; off <<= 1) {
            int y = __shfl_up_sync(0xffffffffu, w, off);
            if (lane >= off) w += y;
        }
        warpsum[lane] = w;
    }
    __syncthreads();
    int incl = x + (wid > 0 ? warpsum[wid - 1] : 0);
    if (i < N_NODES) {
        g_rowptr[i] = incl - v;
        g_dinv[i] = rsqrtf((float)(v + 1));
    }
    if (tid == 1023) g_bsum[blockIdx.x] = incl;
}

__global__ void k_scan2() {
    __shared__ int s[128];
    int t = threadIdx.x;
    s[t] = (t < NBLK_SCAN) ? g_bsum[t] : 0;
    __syncthreads();
    for (int off = 1; off < 128; off <<= 1) {
        int v = (t >= off) ? s[t - off] : 0;
        __syncthreads();
        s[t] += v;
        __syncthreads();
    }
    if (t < NBLK_SCAN) g_boff[t] = (t > 0) ? s[t - 1] : 0;
    if (t == 0) g_rowptr[N_NODES] = s[NBLK_SCAN - 1];
}

__global__ void k_scan3() {
    int i = blockIdx.x * 1024 + threadIdx.x;
    if (i >= N_NODES) return;
    int r = g_rowptr[i] + g_boff[blockIdx.x];
    g_rowptr[i] = r;
    g_cursor[i] = r;
}

__global__ void k_fill() {
    int i = blockIdx.x * blockDim.x + threadIdx.x;
    int base = i * 4;
    if (base >= N_EDGES) return;
    int4 s = *(const int4*)&g_ei32[base];
    int4 d = *(const int4*)&g_ei32[N_EDGES + base];
    g_csrc[atomicAdd(&g_cursor[d.x], 1)] = s.x;
    g_csrc[atomicAdd(&g_cursor[d.y], 1)] = s.y;
    g_csrc[atomicAdd(&g_cursor[d.z], 1)] = s.z;
    g_csrc[atomicAdd(&g_cursor[d.w], 1)] = s.w;
}

// ================= fused encoder + GCN-weight GEMM =================
// xw[r,:] = dinv[r] * ( relu(x[r,:] @ W_enc + b_enc) @ W_gcn )
// 256 threads, 8 warps (4m x 2n), block = 128 rows x 128 cols.
#define LDA 36
#define LDW 132

__global__ __launch_bounds__(256) void k_enc(
    const float* __restrict__ x, const float* __restrict__ W_enc,
    const float* __restrict__ b_enc, const float* __restrict__ W_gcn,
    float* __restrict__ xw)
{
    extern __shared__ float pool[];
    float* xs = pool;             // 2 * 128*36 = 9216
    float* Ws = pool + 9216;      // 128*132   = 16896
    float* Hs = pool + 26112;     // 128*132   = 16896
    __shared__ float sbe[128];

    const int tid = threadIdx.x;
    const int wid = tid >> 5;
    const int wm = wid & 3, wn = wid >> 2;
    const int rowBase = blockIdx.x * 128;

    if (tid < 128) sbe[tid] = b_enc[tid];

    // W_enc -> Ws
#pragma unroll
    for (int i = 0; i < 16; i++) {
        int slot = tid + i * 256;           // float4 slots, 4096 total
        int r = slot >> 5, c4 = (slot & 31) * 4;
        *(float4*)&Ws[r * LDW + c4] = *(const float4*)&W_enc[r * 128 + c4];
    }

    // stage A-chunk kt into xs[buf]
    auto stageA = [&](int buf, int kt) {
        float* dst = xs + buf * (128 * LDA);
#pragma unroll
        for (int i = 0; i < 4; i++) {
            int slot = tid + i * 256;       // 1024 float4
            int r = slot >> 3, c4 = (slot & 7) * 4;
            int gr = rowBase + r;
            cp16(&dst[r * LDA + c4], &x[(size_t)gr * 128 + kt + c4], gr < N_NODES);
        }
        cp_commit();
    };

    wmma::fragment<wmma::accumulator, 16, 16, 8, float> acc[2][4];
#pragma unroll
    for (int mt = 0; mt < 2; mt++)
#pragma unroll
        for (int nt = 0; nt < 4; nt++) wmma::fill_fragment(acc[mt][nt], 0.f);

    stageA(0, 0);

    // ---- stage 1: acc = x @ W_enc ----
    for (int c = 0; c < 4; c++) {
        if (c < 3) { stageA((c + 1) & 1, (c + 1) * 32); cp_wait<1>(); }
        else       cp_wait<0>();
        __syncthreads();
        float* cur = xs + (c & 1) * (128 * LDA);
#pragma unroll
        for (int ks = 0; ks < 4; ks++) {
            int k = ks * 8, kg = c * 32 + k;
            wmma::fragment<wmma::matrix_a, 16, 16, 8, wmma::precision::tf32, wmma::row_major> af[2];
            wmma::fragment<wmma::matrix_b, 16, 16, 8, wmma::precision::tf32, wmma::row_major> bf[4];
#pragma unroll
            for (int mt = 0; mt < 2; mt++) {
                wmma::load_matrix_sync(af[mt], &cur[(wm * 32 + mt * 16) * LDA + k], LDA);
#pragma unroll
                for (int e = 0; e < af[mt].num_elements; e++)
                    af[mt].x[e] = wmma::__float_to_tf32(af[mt].x[e]);
            }
#pragma unroll
            for (int nt = 0; nt < 4; nt++) {
                wmma::load_matrix_sync(bf[nt], &Ws[kg * LDW + wn * 64 + nt * 16], LDW);
#pragma unroll
                for (int e = 0; e < bf[nt].num_elements; e++)
                    bf[nt].x[e] = wmma::__float_to_tf32(bf[nt].x[e]);
            }
#pragma unroll
            for (int mt = 0; mt < 2; mt++)
#pragma unroll
                for (int nt = 0; nt < 4; nt++)
                    wmma::mma_sync(acc[mt][nt], af[mt], bf[nt], acc[mt][nt]);
        }
        __syncthreads();
    }

    // store h1 tile to Hs; load W_gcn over Ws (W_enc reads are done)
#pragma unroll
    for (int mt = 0; mt < 2; mt++)
#pragma unroll
        for (int nt = 0; nt < 4; nt++)
            wmma::store_matrix_sync(&Hs[(wm * 32 + mt * 16) * LDW + wn * 64 + nt * 16],
                                    acc[mt][nt], LDW, wmma::mem_row_major);
#pragma unroll
    for (int i = 0; i < 16; i++) {
        int slot = tid + i * 256;
        int r = slot >> 5, c4 = (slot & 31) * 4;
        *(float4*)&Ws[r * LDW + c4] = *(const float4*)&W_gcn[r * 128 + c4];
    }
    __syncthreads();

    // bias + relu in place on Hs
#pragma unroll
    for (int i = 0; i < 16; i++) {
        int slot = tid + i * 256;
        int r = slot >> 5, c4 = (slot & 31) * 4;
        float4 v = *(float4*)&Hs[r * LDW + c4];
        v.x = fmaxf(v.x + sbe[c4 + 0], 0.f);
        v.y = fmaxf(v.y + sbe[c4 + 1], 0.f);
        v.z = fmaxf(v.z + sbe[c4 + 2], 0.f);
        v.w = fmaxf(v.w + sbe[c4 + 3], 0.f);
        *(float4*)&Hs[r * LDW + c4] = v;
    }
    __syncthreads();

    // ---- stage 2: acc = relu(h1) @ W_gcn ----
#pragma unroll
    for (int mt = 0; mt < 2; mt++)
#pragma unroll
        for (int nt = 0; nt < 4; nt++) wmma::fill_fragment(acc[mt][nt], 0.f);

#pragma unroll
    for (int ks = 0; ks < 16; ks++) {
        int k = ks * 8;
        wmma::fragment<wmma::matrix_a, 16, 16, 8, wmma::precision::tf32, wmma::row_major> af[2];
        wmma::fragment<wmma::matrix_b, 16, 16, 8, wmma::precision::tf32, wmma::row_major> bf[4];
#pragma unroll
        for (int mt = 0; mt < 2; mt++) {
            wmma::load_matrix_sync(af[mt], &Hs[(wm * 32 + mt * 16) * LDW + k], LDW);
#pragma unroll
            for (int e = 0; e < af[mt].num_elements; e++)
                af[mt].x[e] = wmma::__float_to_tf32(af[mt].x[e]);
        }
#pragma unroll
        for (int nt = 0; nt < 4; nt++) {
            wmma::load_matrix_sync(bf[nt], &Ws[k * LDW + wn * 64 + nt * 16], LDW);
#pragma unroll
            for (int e = 0; e < bf[nt].num_elements; e++)
                bf[nt].x[e] = wmma::__float_to_tf32(bf[nt].x[e]);
        }
#pragma unroll
        for (int mt = 0; mt < 2; mt++)
#pragma unroll
            for (int nt = 0; nt < 4; nt++)
                wmma::mma_sync(acc[mt][nt], af[mt], bf[nt], acc[mt][nt]);
    }
    __syncthreads();

    // store -> Hs, then dinv-scaled write to gmem
#pragma unroll
    for (int mt = 0; mt < 2; mt++)
#pragma unroll
        for (int nt = 0; nt < 4; nt++)
            wmma::store_matrix_sync(&Hs[(wm * 32 + mt * 16) * LDW + wn * 64 + nt * 16],
                                    acc[mt][nt], LDW, wmma::mem_row_major);
    __syncthreads();

#pragma unroll
    for (int i = 0; i < 16; i++) {
        int slot = tid + i * 256;
        int r = slot >> 5, c4 = (slot & 31) * 4;
        int gr = rowBase + r;
        float di = g_dinv[min(gr, N_NODES - 1)];
        float4 v = *(float4*)&Hs[r * LDW + c4];
        v.x *= di; v.y *= di; v.z *= di; v.w *= di;
        *(float4*)&xw[(size_t)gr * 128 + c4] = v;
    }
}

// ---------------- GCN aggregation: warp per node (xw pre-scaled) ----------------
__global__ void k_agg(const float* __restrict__ b_gcn) {
    int gw = (blockIdx.x * blockDim.x + threadIdx.x) >> 5;
    int lane = threadIdx.x & 31;
    if (gw >= N_NODES) return;

    int beg = g_rowptr[gw];
    int end = g_rowptr[gw + 1];

    float4 acc = make_float4(0.f, 0.f, 0.f, 0.f);
    for (int base = beg; base < end; base += 32) {
        int e = base + lane;
        int s = (e < end) ? g_csrc[e] : 0;
        int cnt = min(32, end - base);
        for (int j = 0; j < cnt; j++) {
            int sj = __shfl_sync(0xffffffffu, s, j);
            float4 v = *(const float4*)&g_xw[(size_t)sj * H + lane * 4];
            acc.x += v.x; acc.y += v.y; acc.z += v.z; acc.w += v.w;
        }
    }

    float di = g_dinv[gw];
    float4 self = *(const float4*)&g_xw[(size_t)gw * H + lane * 4];
    float4 b    = *(const float4*)&b_gcn[lane * 4];
    float4 o;
    o.x = fmaxf(fmaf(di, acc.x + self.x, b.x), 0.f);
    o.y = fmaxf(fmaf(di, acc.y + self.y, b.y), 0.f);
    o.z = fmaxf(fmaf(di, acc.z + self.z, b.z), 0.f);
    o.w = fmaxf(fmaf(di, acc.w + self.w, b.w), 0.f);
    *(float4*)&g_h2[(size_t)gw * H + lane * 4] = o;
}

// ========== fused MLP head: out = relu(h2 @ W1 + b1) @ W2 + b2 ==========
// 512 threads, 16 warps (4m x 4n), block = 128 rows x 256 cols.
#define LDB1 264

__global__ __launch_bounds__(512) void k_w1out(
    const float* __restrict__ W1, const float* __restrict__ b1,
    const float* __restrict__ W2, const float* __restrict__ b2,
    float* __restrict__ out)
{
    extern __shared__ float pool[];
    float* xs = pool;             // 2 * 128*36 = 9216
    float* Bs = pool + 9216;      // 2 * 32*264 = 16896
    float* Ts = pool;             // alias: 128*264 = 33792
    __shared__ float sW2[HQ * A_DIM];
    __shared__ float sb1[HQ];
    __shared__ float sb2[A_DIM];

    const int tid = threadIdx.x;
    const int wid = tid >> 5, lane = tid & 31;
    const int wm = wid & 3, wn = wid >> 2;
    const int rowBase = blockIdx.x * 128;

    for (int j = tid; j < HQ * A_DIM; j += 512) sW2[j] = W2[j];
    for (int j = tid; j < HQ; j += 512) sb1[j] = b1[j];
    if (tid < A_DIM) sb2[tid] = b2[tid];

    auto stage = [&](int buf, int kt) {
        float* ad = xs + buf * (128 * LDA);
#pragma unroll
        for (int i = 0; i < 2; i++) {
            int slot = tid + i * 512;       // 1024 float4
            int r = slot >> 3, c4 = (slot & 7) * 4;
            cp16(&ad[r * LDA + c4], &g_h2[(size_t)(rowBase + r) * 128 + kt + c4], true);
        }
        float* bd = Bs + buf * (32 * LDB1);
#pragma unroll
        for (int i = 0; i < 4; i++) {
            int slot = tid + i * 512;       // 2048 float4
            int r = slot >> 6, c4 = (slot & 63) * 4;
            cp16(&bd[r * LDB1 + c4], &W1[(size_t)(kt + r) * 256 + c4], true);
        }
        cp_commit();
    };

    wmma::fragment<wmma::accumulator, 16, 16, 8, float> acc[2][4];
#pragma unroll
    for (int mt = 0; mt < 2; mt++)
#pragma unroll
        for (int nt = 0; nt < 4; nt++) wmma::fill_fragment(acc[mt][nt], 0.f);

    stage(0, 0);
    for (int c = 0; c < 4; c++) {
        if (c < 3) { stage((c + 1) & 1, (c + 1) * 32); cp_wait<1>(); }
        else       cp_wait<0>();
        __syncthreads();
        float* ac = xs + (c & 1) * (128 * LDA);
        float* bc = Bs + (c & 1) * (32 * LDB1);
#pragma unroll
        for (int ks = 0; ks < 4; ks++) {
            int k = ks * 8;
            wmma::fragment<wmma::matrix_a, 16, 16, 8, wmma::precision::tf32, wmma::row_major> af[2];
            wmma::fragment<wmma::matrix_b, 16, 16, 8, wmma::precision::tf32, wmma::row_major> bf[4];
#pragma unroll
            for (int mt = 0; mt < 2; mt++) {
                wmma::load_matrix_sync(af[mt], &ac[(wm * 32 + mt * 16) * LDA + k], LDA);
#pragma unroll
                for (int e = 0; e < af[mt].num_elements; e++)
                    af[mt].x[e] = wmma::__float_to_tf32(af[mt].x[e]);
            }
#pragma unroll
            for (int nt = 0; nt < 4; nt++) {
                wmma::load_matrix_sync(bf[nt], &bc[k * LDB1 + wn * 64 + nt * 16], LDB1);
#pragma unroll
                for (int e = 0; e < bf[nt].num_elements; e++)
                    bf[nt].x[e] = wmma::__float_to_tf32(bf[nt].x[e]);
            }
#pragma unroll
            for (int mt = 0; mt < 2; mt++)
#pragma unroll
                for (int nt = 0; nt < 4; nt++)
                    wmma::mma_sync(acc[mt][nt], af[mt], bf[nt], acc[mt][nt]);
        }
        __syncthreads();
    }

    // t tile -> Ts (aliases staging; all stage reads done)
#pragma unroll
    for (int mt = 0; mt < 2; mt++)
#pragma unroll
        for (int nt = 0; nt < 4; nt++)
            wmma::store_matrix_sync(&Ts[(wm * 32 + mt * 16) * LDB1 + wn * 64 + nt * 16],
                                    acc[mt][nt], LDB1, wmma::mem_row_major);
    __syncthreads();

    // phase 2: per-warp 8 rows, relu(t+b1) @ W2 + b2
    int r0 = wid * 8;
#pragma unroll
    for (int rr = 0; rr < 8; rr++) {
        int r = r0 + rr;
        int gr = rowBase + r;
        float tv[8];
#pragma unroll
        for (int j = 0; j < 8; j++) {
            int cc = lane + 32 * j;
            tv[j] = fmaxf(Ts[r * LDB1 + cc] + sb1[cc], 0.f);
        }
        float o[A_DIM];
#pragma unroll
        for (int a = 0; a < A_DIM; a++) {
            float p = 0.f;
#pragma unroll
            for (int j = 0; j < 8; j++)
                p = fmaf(tv[j], sW2[(lane + 32 * j) * A_DIM + a], p);
#pragma unroll
            for (int off = 16; off; off >>= 1) p += __shfl_xor_sync(0xffffffffu, p, off);
            o[a] = p;
        }
        if (lane == 0 && gr < N_NODES) {
#pragma unroll
            for (int a = 0; a < A_DIM; a++)
                out[(size_t)gr * A_DIM + a] = o[a] + sb2[a];
        }
    }
}

// ---------------- launcher ----------------
extern "C" void kernel_launch(void* const* d_in, const int* in_sizes, int n_in,
                              void* d_out, int out_size) {
    const float* x     = (const float*)d_in[0];
    const void*  ei    = d_in[1];
    const float* W_enc = (const float*)d_in[2];
    const float* b_enc = (const float*)d_in[3];
    const float* W_gcn = (const float*)d_in[4];
    const float* b_gcn = (const float*)d_in[5];
    const float* W1    = (const float*)d_in[6];
    const float* b1    = (const float*)d_in[7];
    const float* W2    = (const float*)d_in[8];
    const float* b2    = (const float*)d_in[9];
    float* out = (float*)d_out;

    float* xw = nullptr;
    cudaGetSymbolAddress((void**)&xw, g_xw);

    static bool attr_done = false;
    if (!attr_done) {
        cudaFuncSetAttribute(k_enc,   cudaFuncAttributeMaxDynamicSharedMemorySize, 43008 * 4);
        cudaFuncSetAttribute(k_w1out, cudaFuncAttributeMaxDynamicSharedMemorySize, 33792 * 4);
        attr_done = true;
    }

    // CSR build
    k_detect<<<1, 32>>>(ei);
    k_zero_deg<<<cdiv(N_NODES, 256), 256>>>();
    k_cvt_hist<<<cdiv(N_EDGES, 256), 256>>>(ei);   // 2 elems/thread over 2E
    k_scan1<<<NBLK_SCAN, 1024>>>();
    k_scan2<<<1, 128>>>();
    k_scan3<<<NBLK_SCAN, 1024>>>();
    k_fill<<<cdiv(N_EDGES / 4, 256), 256>>>();

    // xw = dinv * (relu(x@W_enc+b_enc) @ W_gcn)
    k_enc<<<N_PAD / 128, 256, 43008 * 4>>>(x, W_enc, b_enc, W_gcn, xw);
    // h2 = relu(dinv*(agg + self) + b_gcn)
    k_agg<<<cdiv(N_NODES * 32, 256), 256>>>(b_gcn);
    // out = relu(h2@W1+b1)@W2 + b2
    k_w1out<<<N_PAD / 128, 512, 33792 * 4>>>(W1, b1, W2, b2, out);
}

// round 4
// speedup vs baseline: 1.7685x; 1.0996x over previous
#include <cuda_runtime.h>
#include <cuda_fp16.h>
#include <mma.h>
#include <cstdint>

using namespace nvcuda;

#define N_NODES 100000
#define N_PAD   100096   // 782 * 128
#define N_EDGES 3200000
#define H 128
#define HQ 256
#define A_DIM 10
#define NBLK_SCAN 98

static inline int cdiv(int a, int b) { return (a + b - 1) / b; }

// ---------------- scratch ----------------
__device__ __half g_xw16[(size_t)N_PAD * H];  // fp16 dinv-scaled relu(x@We+be)@Wg
__device__ float  g_h2[(size_t)N_PAD * H];    // relu(gcn agg)
__device__ float  g_dinv[N_NODES];
__device__ int    g_deg[N_NODES];
__device__ int    g_rowptr[N_NODES + 1];
__device__ int    g_cursor[N_NODES];
__device__ int    g_csrc[N_EDGES];
__device__ int    g_dst32[N_EDGES];
__device__ int    g_is32;
__device__ int    g_bsum[NBLK_SCAN];
__device__ int    g_boff[NBLK_SCAN];

// ---------------- cp.async helpers ----------------
__device__ __forceinline__ void cp16(void* s, const void* g, bool p) {
    uint32_t sa = (uint32_t)__cvta_generic_to_shared(s);
    int sz = p ? 16 : 0;
    asm volatile("cp.async.cg.shared.global [%0], [%1], 16, %2;\n"
                 :: "r"(sa), "l"(g), "r"(sz));
}
__device__ __forceinline__ void cp_commit() {
    asm volatile("cp.async.commit_group;\n");
}
template <int NN>
__device__ __forceinline__ void cp_wait() {
    asm volatile("cp.async.wait_group %0;\n" :: "n"(NN));
}

// ---------------- edge dtype detect ----------------
__global__ void k_detect(const void* ei) {
    if (threadIdx.x == 0 && blockIdx.x == 0) {
        const long long* p = (const long long*)ei;
        int is32 = 0;
        for (int i = 0; i < 64; i++) {
            long long v = p[i];
            if (v < 0 || v >= (long long)N_NODES) { is32 = 1; break; }
        }
        g_is32 = is32;
    }
}

__global__ void k_zero_deg() {
    int i = blockIdx.x * blockDim.x + threadIdx.x;
    if (i < N_NODES) g_deg[i] = 0;
}

// histogram over dst half only; cache dst as int32
__global__ void k_hist(const void* ei) {
    int i = blockIdx.x * blockDim.x + threadIdx.x;   // 2 edges/thread
    int base = i * 2;
    if (base >= N_EDGES) return;
    int v0, v1;
    if (g_is32) {
        int2 p = ((const int2*)ei)[N_EDGES / 2 + i];
        v0 = p.x; v1 = p.y;
    } else {
        longlong2 p = ((const longlong2*)ei)[N_EDGES / 2 + i];
        v0 = (int)p.x; v1 = (int)p.y;
    }
    *(int2*)&g_dst32[base] = make_int2(v0, v1);
    atomicAdd(&g_deg[v0], 1);
    atomicAdd(&g_deg[v1], 1);
}

// ---------- 3-phase scan ----------
__global__ void k_scan1() {
    __shared__ int warpsum[32];
    int tid = threadIdx.x, lane = tid & 31, wid = tid >> 5;
    int i = blockIdx.x * 1024 + tid;
    int v = (i < N_NODES) ? g_deg[i] : 0;
    int x = v;
#pragma unroll
    for (int off = 1; off < 32; off <<= 1) {
        int y = __shfl_up_sync(0xffffffffu, x, off);
        if (lane >= off) x += y;
    }
    if (lane == 31) warpsum[wid] = x;
    __syncthreads();
    if (wid == 0) {
        int w = warpsum[lane];
#pragma unroll
        for (int off = 1; off < 32; off <<= 1) {
            int y = __shfl_up_sync(0xffffffffu, w, off);
            if (lane >= off) w += y;
        }
        warpsum[lane] = w;
    }
    __syncthreads();
    int incl = x + (wid > 0 ? warpsum[wid - 1] : 0);
    if (i < N_NODES) {
        g_rowptr[i] = incl - v;
        g_dinv[i] = rsqrtf((float)(v + 1));
    }
    if (tid == 1023) g_bsum[blockIdx.x] = incl;
}

__global__ void k_scan2() {
    __shared__ int s[128];
    int t = threadIdx.x;
    s[t] = (t < NBLK_SCAN) ? g_bsum[t] : 0;
    __syncthreads();
    for (int off = 1; off < 128; off <<= 1) {
        int v = (t >= off) ? s[t - off] : 0;
        __syncthreads();
        s[t] += v;
        __syncthreads();
    }
    if (t < NBLK_SCAN) g_boff[t] = (t > 0) ? s[t - 1] : 0;
    if (t == 0) g_rowptr[N_NODES] = s[NBLK_SCAN - 1];
}

__global__ void k_scan3() {
    int i = blockIdx.x * 1024 + threadIdx.x;
    if (i >= N_NODES) return;
    int r = g_rowptr[i] + g_boff[blockIdx.x];
    g_rowptr[i] = r;
    g_cursor[i] = r;
}

// fill CSR: src read straight from edge_index
__global__ void k_fill(const void* ei) {
    int i = blockIdx.x * blockDim.x + threadIdx.x;   // 4 edges/thread
    int base = i * 4;
    if (base >= N_EDGES) return;
    int s0, s1, s2, s3;
    if (g_is32) {
        int4 sv = ((const int4*)ei)[i];
        s0 = sv.x; s1 = sv.y; s2 = sv.z; s3 = sv.w;
    } else {
        longlong2 a = ((const longlong2*)ei)[i * 2];
        longlong2 b = ((const longlong2*)ei)[i * 2 + 1];
        s0 = (int)a.x; s1 = (int)a.y; s2 = (int)b.x; s3 = (int)b.y;
    }
    int4 d = *(const int4*)&g_dst32[base];
    g_csrc[atomicAdd(&g_cursor[d.x], 1)] = s0;
    g_csrc[atomicAdd(&g_cursor[d.y], 1)] = s1;
    g_csrc[atomicAdd(&g_cursor[d.z], 1)] = s2;
    g_csrc[atomicAdd(&g_cursor[d.w], 1)] = s3;
}

// ================= fused encoder + GCN-weight GEMM =================
// xw16[r,:] = fp16( dinv[r] * ( relu(x[r,:] @ W_enc + b_enc) @ W_gcn ) )
#define LDA 36
#define LDW 132

__global__ __launch_bounds__(256) void k_enc(
    const float* __restrict__ x, const float* __restrict__ W_enc,
    const float* __restrict__ b_enc, const float* __restrict__ W_gcn)
{
    extern __shared__ float pool[];
    float* xs = pool;             // 2 * 128*36 = 9216
    float* Ws = pool + 9216;      // 128*132   = 16896
    float* Hs = pool + 26112;     // 128*132   = 16896
    __shared__ float sbe[128];

    const int tid = threadIdx.x;
    const int wid = tid >> 5;
    const int wm = wid & 3, wn = wid >> 2;
    const int rowBase = blockIdx.x * 128;

    if (tid < 128) sbe[tid] = b_enc[tid];

#pragma unroll
    for (int i = 0; i < 16; i++) {
        int slot = tid + i * 256;
        int r = slot >> 5, c4 = (slot & 31) * 4;
        *(float4*)&Ws[r * LDW + c4] = *(const float4*)&W_enc[r * 128 + c4];
    }

    auto stageA = [&](int buf, int kt) {
        float* dst = xs + buf * (128 * LDA);
#pragma unroll
        for (int i = 0; i < 4; i++) {
            int slot = tid + i * 256;
            int r = slot >> 3, c4 = (slot & 7) * 4;
            int gr = rowBase + r;
            cp16(&dst[r * LDA + c4], &x[(size_t)gr * 128 + kt + c4], gr < N_NODES);
        }
        cp_commit();
    };

    wmma::fragment<wmma::accumulator, 16, 16, 8, float> acc[2][4];
#pragma unroll
    for (int mt = 0; mt < 2; mt++)
#pragma unroll
        for (int nt = 0; nt < 4; nt++) wmma::fill_fragment(acc[mt][nt], 0.f);

    stageA(0, 0);

    for (int c = 0; c < 4; c++) {
        if (c < 3) { stageA((c + 1) & 1, (c + 1) * 32); cp_wait<1>(); }
        else       cp_wait<0>();
        __syncthreads();
        float* cur = xs + (c & 1) * (128 * LDA);
#pragma unroll
        for (int ks = 0; ks < 4; ks++) {
            int k = ks * 8, kg = c * 32 + k;
            wmma::fragment<wmma::matrix_a, 16, 16, 8, wmma::precision::tf32, wmma::row_major> af[2];
            wmma::fragment<wmma::matrix_b, 16, 16, 8, wmma::precision::tf32, wmma::row_major> bf[4];
#pragma unroll
            for (int mt = 0; mt < 2; mt++) {
                wmma::load_matrix_sync(af[mt], &cur[(wm * 32 + mt * 16) * LDA + k], LDA);
#pragma unroll
                for (int e = 0; e < af[mt].num_elements; e++)
                    af[mt].x[e] = wmma::__float_to_tf32(af[mt].x[e]);
            }
#pragma unroll
            for (int nt = 0; nt < 4; nt++) {
                wmma::load_matrix_sync(bf[nt], &Ws[kg * LDW + wn * 64 + nt * 16], LDW);
#pragma unroll
                for (int e = 0; e < bf[nt].num_elements; e++)
                    bf[nt].x[e] = wmma::__float_to_tf32(bf[nt].x[e]);
            }
#pragma unroll
            for (int mt = 0; mt < 2; mt++)
#pragma unroll
                for (int nt = 0; nt < 4; nt++)
                    wmma::mma_sync(acc[mt][nt], af[mt], bf[nt], acc[mt][nt]);
        }
        __syncthreads();
    }

#pragma unroll
    for (int mt = 0; mt < 2; mt++)
#pragma unroll
        for (int nt = 0; nt < 4; nt++)
            wmma::store_matrix_sync(&Hs[(wm * 32 + mt * 16) * LDW + wn * 64 + nt * 16],
                                    acc[mt][nt], LDW, wmma::mem_row_major);
#pragma unroll
    for (int i = 0; i < 16; i++) {
        int slot = tid + i * 256;
        int r = slot >> 5, c4 = (slot & 31) * 4;
        *(float4*)&Ws[r * LDW + c4] = *(const float4*)&W_gcn[r * 128 + c4];
    }
    __syncthreads();

#pragma unroll
    for (int i = 0; i < 16; i++) {
        int slot = tid + i * 256;
        int r = slot >> 5, c4 = (slot & 31) * 4;
        float4 v = *(float4*)&Hs[r * LDW + c4];
        v.x = fmaxf(v.x + sbe[c4 + 0], 0.f);
        v.y = fmaxf(v.y + sbe[c4 + 1], 0.f);
        v.z = fmaxf(v.z + sbe[c4 + 2], 0.f);
        v.w = fmaxf(v.w + sbe[c4 + 3], 0.f);
        *(float4*)&Hs[r * LDW + c4] = v;
    }
    __syncthreads();

#pragma unroll
    for (int mt = 0; mt < 2; mt++)
#pragma unroll
        for (int nt = 0; nt < 4; nt++) wmma::fill_fragment(acc[mt][nt], 0.f);

#pragma unroll
    for (int ks = 0; ks < 16; ks++) {
        int k = ks * 8;
        wmma::fragment<wmma::matrix_a, 16, 16, 8, wmma::precision::tf32, wmma::row_major> af[2];
        wmma::fragment<wmma::matrix_b, 16, 16, 8, wmma::precision::tf32, wmma::row_major> bf[4];
#pragma unroll
        for (int mt = 0; mt < 2; mt++) {
            wmma::load_matrix_sync(af[mt], &Hs[(wm * 32 + mt * 16) * LDW + k], LDW);
#pragma unroll
            for (int e = 0; e < af[mt].num_elements; e++)
                af[mt].x[e] = wmma::__float_to_tf32(af[mt].x[e]);
        }
#pragma unroll
        for (int nt = 0; nt < 4; nt++) {
            wmma::load_matrix_sync(bf[nt], &Ws[k * LDW + wn * 64 + nt * 16], LDW);
#pragma unroll
            for (int e = 0; e < bf[nt].num_elements; e++)
                bf[nt].x[e] = wmma::__float_to_tf32(bf[nt].x[e]);
        }
#pragma unroll
        for (int mt = 0; mt < 2; mt++)
#pragma unroll
            for (int nt = 0; nt < 4; nt++)
                wmma::mma_sync(acc[mt][nt], af[mt], bf[nt], acc[mt][nt]);
    }
    __syncthreads();

#pragma unroll
    for (int mt = 0; mt < 2; mt++)
#pragma unroll
        for (int nt = 0; nt < 4; nt++)
            wmma::store_matrix_sync(&Hs[(wm * 32 + mt * 16) * LDW + wn * 64 + nt * 16],
                                    acc[mt][nt], LDW, wmma::mem_row_major);
    __syncthreads();

    // dinv scale + fp16 pack + store (8B per thread-slot)
#pragma unroll
    for (int i = 0; i < 16; i++) {
        int slot = tid + i * 256;
        int r = slot >> 5, c4 = (slot & 31) * 4;
        int gr = rowBase + r;
        float di = g_dinv[min(gr, N_NODES - 1)];
        float4 v = *(float4*)&Hs[r * LDW + c4];
        __half2 h0 = __floats2half2_rn(v.x * di, v.y * di);
        __half2 h1 = __floats2half2_rn(v.z * di, v.w * di);
        uint2 u;
        u.x = *(uint32_t*)&h0;
        u.y = *(uint32_t*)&h1;
        *(uint2*)&g_xw16[(size_t)gr * 128 + c4] = u;
    }
}

// ---------------- GCN aggregation: warp per node, fp16 gather ----------------
__device__ __forceinline__ void agg_row(float4& acc, int sj, int lane) {
    uint2 u = *(const uint2*)&g_xw16[(size_t)sj * 128 + lane * 4];
    float2 f0 = __half22float2(*(__half2*)&u.x);
    float2 f1 = __half22float2(*(__half2*)&u.y);
    acc.x += f0.x; acc.y += f0.y; acc.z += f1.x; acc.w += f1.y;
}

__global__ void k_agg(const float* __restrict__ b_gcn) {
    int gw = (blockIdx.x * blockDim.x + threadIdx.x) >> 5;
    int lane = threadIdx.x & 31;
    if (gw >= N_NODES) return;

    int beg = g_rowptr[gw];
    int end = g_rowptr[gw + 1];

    float4 acc = make_float4(0.f, 0.f, 0.f, 0.f);
    for (int base = beg; base < end; base += 32) {
        int e = base + lane;
        int s = (e < end) ? g_csrc[e] : 0;
        int cnt = min(32, end - base);
        if (cnt == 32) {
#pragma unroll
            for (int j = 0; j < 32; j++)
                agg_row(acc, __shfl_sync(0xffffffffu, s, j), lane);
        } else {
            for (int j = 0; j < cnt; j++)
                agg_row(acc, __shfl_sync(0xffffffffu, s, j), lane);
        }
    }

    float di = g_dinv[gw];
    float4 self = make_float4(0.f, 0.f, 0.f, 0.f);
    agg_row(self, gw, lane);
    float4 b = *(const float4*)&b_gcn[lane * 4];
    float4 o;
    o.x = fmaxf(fmaf(di, acc.x + self.x, b.x), 0.f);
    o.y = fmaxf(fmaf(di, acc.y + self.y, b.y), 0.f);
    o.z = fmaxf(fmaf(di, acc.z + self.z, b.z), 0.f);
    o.w = fmaxf(fmaf(di, acc.w + self.w, b.w), 0.f);
    *(float4*)&g_h2[(size_t)gw * H + lane * 4] = o;
}

// ========== fused MLP head: out = relu(h2 @ W1 + b1) @ W2 + b2 ==========
#define LDB1 264

__global__ __launch_bounds__(512) void k_w1out(
    const float* __restrict__ W1, const float* __restrict__ b1,
    const float* __restrict__ W2, const float* __restrict__ b2,
    float* __restrict__ out)
{
    extern __shared__ float pool[];
    float* xs = pool;             // 2 * 128*36 = 9216
    float* Bs = pool + 9216;      // 2 * 32*264 = 16896
    float* Ts = pool;             // alias: 128*264 = 33792
    __shared__ float sW2[HQ * A_DIM];
    __shared__ float sb1[HQ];
    __shared__ float sb2[A_DIM];

    const int tid = threadIdx.x;
    const int wid = tid >> 5, lane = tid & 31;
    const int wm = wid & 3, wn = wid >> 2;
    const int rowBase = blockIdx.x * 128;

    for (int j = tid; j < HQ * A_DIM; j += 512) sW2[j] = W2[j];
    for (int j = tid; j < HQ; j += 512) sb1[j] = b1[j];
    if (tid < A_DIM) sb2[tid] = b2[tid];

    auto stage = [&](int buf, int kt) {
        float* ad = xs + buf * (128 * LDA);
#pragma unroll
        for (int i = 0; i < 2; i++) {
            int slot = tid + i * 512;
            int r = slot >> 3, c4 = (slot & 7) * 4;
            cp16(&ad[r * LDA + c4], &g_h2[(size_t)(rowBase + r) * 128 + kt + c4], true);
        }
        float* bd = Bs + buf * (32 * LDB1);
#pragma unroll
        for (int i = 0; i < 4; i++) {
            int slot = tid + i * 512;
            int r = slot >> 6, c4 = (slot & 63) * 4;
            cp16(&bd[r * LDB1 + c4], &W1[(size_t)(kt + r) * 256 + c4], true);
        }
        cp_commit();
    };

    wmma::fragment<wmma::accumulator, 16, 16, 8, float> acc[2][4];
#pragma unroll
    for (int mt = 0; mt < 2; mt++)
#pragma unroll
        for (int nt = 0; nt < 4; nt++) wmma::fill_fragment(acc[mt][nt], 0.f);

    stage(0, 0);
    for (int c = 0; c < 4; c++) {
        if (c < 3) { stage((c + 1) & 1, (c + 1) * 32); cp_wait<1>(); }
        else       cp_wait<0>();
        __syncthreads();
        float* ac = xs + (c & 1) * (128 * LDA);
        float* bc = Bs + (c & 1) * (32 * LDB1);
#pragma unroll
        for (int ks = 0; ks < 4; ks++) {
            int k = ks * 8;
            wmma::fragment<wmma::matrix_a, 16, 16, 8, wmma::precision::tf32, wmma::row_major> af[2];
            wmma::fragment<wmma::matrix_b, 16, 16, 8, wmma::precision::tf32, wmma::row_major> bf[4];
#pragma unroll
            for (int mt = 0; mt < 2; mt++) {
                wmma::load_matrix_sync(af[mt], &ac[(wm * 32 + mt * 16) * LDA + k], LDA);
#pragma unroll
                for (int e = 0; e < af[mt].num_elements; e++)
                    af[mt].x[e] = wmma::__float_to_tf32(af[mt].x[e]);
            }
#pragma unroll
            for (int nt = 0; nt < 4; nt++) {
                wmma::load_matrix_sync(bf[nt], &bc[k * LDB1 + wn * 64 + nt * 16], LDB1);
#pragma unroll
                for (int e = 0; e < bf[nt].num_elements; e++)
                    bf[nt].x[e] = wmma::__float_to_tf32(bf[nt].x[e]);
            }
#pragma unroll
            for (int mt = 0; mt < 2; mt++)
#pragma unroll
                for (int nt = 0; nt < 4; nt++)
                    wmma::mma_sync(acc[mt][nt], af[mt], bf[nt], acc[mt][nt]);
        }
        __syncthreads();
    }

#pragma unroll
    for (int mt = 0; mt < 2; mt++)
#pragma unroll
        for (int nt = 0; nt < 4; nt++)
            wmma::store_matrix_sync(&Ts[(wm * 32 + mt * 16) * LDB1 + wn * 64 + nt * 16],
                                    acc[mt][nt], LDB1, wmma::mem_row_major);
    __syncthreads();

    int r0 = wid * 8;
#pragma unroll
    for (int rr = 0; rr < 8; rr++) {
        int r = r0 + rr;
        int gr = rowBase + r;
        float tv[8];
#pragma unroll
        for (int j = 0; j < 8; j++) {
            int cc = lane + 32 * j;
            tv[j] = fmaxf(Ts[r * LDB1 + cc] + sb1[cc], 0.f);
        }
        float o[A_DIM];
#pragma unroll
        for (int a = 0; a < A_DIM; a++) {
            float p = 0.f;
#pragma unroll
            for (int j = 0; j < 8; j++)
                p = fmaf(tv[j], sW2[(lane + 32 * j) * A_DIM + a], p);
#pragma unroll
            for (int off = 16; off; off >>= 1) p += __shfl_xor_sync(0xffffffffu, p, off);
            o[a] = p;
        }
        if (lane == 0 && gr < N_NODES) {
#pragma unroll
            for (int a = 0; a < A_DIM; a++)
                out[(size_t)gr * A_DIM + a] = o[a] + sb2[a];
        }
    }
}

// ---------------- launcher ----------------
extern "C" void kernel_launch(void* const* d_in, const int* in_sizes, int n_in,
                              void* d_out, int out_size) {
    const float* x     = (const float*)d_in[0];
    const void*  ei    = d_in[1];
    const float* W_enc = (const float*)d_in[2];
    const float* b_enc = (const float*)d_in[3];
    const float* W_gcn = (const float*)d_in[4];
    const float* b_gcn = (const float*)d_in[5];
    const float* W1    = (const float*)d_in[6];
    const float* b1    = (const float*)d_in[7];
    const float* W2    = (const float*)d_in[8];
    const float* b2    = (const float*)d_in[9];
    float* out = (float*)d_out;

    static bool attr_done = false;
    if (!attr_done) {
        cudaFuncSetAttribute(k_enc,   cudaFuncAttributeMaxDynamicSharedMemorySize, 43008 * 4);
        cudaFuncSetAttribute(k_w1out, cudaFuncAttributeMaxDynamicSharedMemorySize, 33792 * 4);
        attr_done = true;
    }

    // CSR build
    k_detect<<<1, 32>>>(ei);
    k_zero_deg<<<cdiv(N_NODES, 256), 256>>>();
    k_hist<<<cdiv(N_EDGES / 2, 256), 256>>>(ei);
    k_scan1<<<NBLK_SCAN, 1024>>>();
    k_scan2<<<1, 128>>>();
    k_scan3<<<NBLK_SCAN, 1024>>>();
    k_fill<<<cdiv(N_EDGES / 4, 256), 256>>>(ei);

    // xw16 = fp16(dinv * (relu(x@W_enc+b_enc) @ W_gcn))
    k_enc<<<N_PAD / 128, 256, 43008 * 4>>>(x, W_enc, b_enc, W_gcn);
    // h2 = relu(dinv*(agg + self) + b_gcn)
    k_agg<<<cdiv(N_NODES * 32, 256), 256>>>(b_gcn);
    // out = relu(h2@W1+b1)@W2 + b2
    k_w1out<<<N_PAD / 128, 512, 33792 * 4>>>(W1, b1, W2, b2, out);
}

// round 5
// speedup vs baseline: 2.1495x; 1.2154x over previous
#include <cuda_runtime.h>
#include <cuda_fp16.h>
#include <mma.h>
#include <cstdint>

using namespace nvcuda;

#define N_NODES 100000
#define N_PAD   100096   // 782 * 128
#define N_EDGES 3200000
#define H 128
#define HQ 256
#define A_DIM 10
#define NBLK_SCAN 98

static inline int cdiv(int a, int b) { return (a + b - 1) / b; }

// ---------------- scratch ----------------
__device__ __half g_xw16[(size_t)N_PAD * H];  // fp16 dinv-scaled relu(x@We+be)@Wg
__device__ __half g_h216[(size_t)N_PAD * H];  // fp16 relu(gcn agg); pad rows stay 0
__device__ __half g_W116[HQ * H];             // fp16 W1 [128,256]
__device__ float  g_dinv[N_NODES];
__device__ int    g_deg[N_NODES];
__device__ int    g_rowptr[N_NODES + 1];
__device__ int    g_cursor[N_NODES];
__device__ int    g_csrc[N_EDGES];
__device__ int    g_dst32[N_EDGES];
__device__ int    g_is32;
__device__ int    g_bsum[NBLK_SCAN];
__device__ int    g_boff[NBLK_SCAN];

// ---------------- cp.async helpers ----------------
__device__ __forceinline__ void cp16(void* s, const void* g, bool p) {
    uint32_t sa = (uint32_t)__cvta_generic_to_shared(s);
    int sz = p ? 16 : 0;
    asm volatile("cp.async.cg.shared.global [%0], [%1], 16, %2;\n"
                 :: "r"(sa), "l"(g), "r"(sz));
}
__device__ __forceinline__ void cp_commit() {
    asm volatile("cp.async.commit_group;\n");
}
template <int NN>
__device__ __forceinline__ void cp_wait() {
    asm volatile("cp.async.wait_group %0;\n" :: "n"(NN));
}

// ---------------- W1 -> fp16 ----------------
__global__ void k_cvtW1(const float* __restrict__ W1) {
    int i = blockIdx.x * blockDim.x + threadIdx.x;   // 4 elems/thread
    int base = i * 4;
    if (base >= HQ * H) return;
    float4 v = *(const float4*)&W1[base];
    __half2 h0 = __floats2half2_rn(v.x, v.y);
    __half2 h1 = __floats2half2_rn(v.z, v.w);
    uint2 u;
    u.x = *(uint32_t*)&h0;
    u.y = *(uint32_t*)&h1;
    *(uint2*)&g_W116[base] = u;
}

// ---------------- edge dtype detect ----------------
__global__ void k_detect(const void* ei) {
    if (threadIdx.x == 0 && blockIdx.x == 0) {
        const long long* p = (const long long*)ei;
        int is32 = 0;
        for (int i = 0; i < 64; i++) {
            long long v = p[i];
            if (v < 0 || v >= (long long)N_NODES) { is32 = 1; break; }
        }
        g_is32 = is32;
    }
}

__global__ void k_zero_deg() {
    int i = blockIdx.x * blockDim.x + threadIdx.x;
    if (i < N_NODES) g_deg[i] = 0;
}

// histogram over dst half only; cache dst as int32
__global__ void k_hist(const void* ei) {
    int i = blockIdx.x * blockDim.x + threadIdx.x;   // 2 edges/thread
    int base = i * 2;
    if (base >= N_EDGES) return;
    int v0, v1;
    if (g_is32) {
        int2 p = ((const int2*)ei)[N_EDGES / 2 + i];
        v0 = p.x; v1 = p.y;
    } else {
        longlong2 p = ((const longlong2*)ei)[N_EDGES / 2 + i];
        v0 = (int)p.x; v1 = (int)p.y;
    }
    *(int2*)&g_dst32[base] = make_int2(v0, v1);
    atomicAdd(&g_deg[v0], 1);
    atomicAdd(&g_deg[v1], 1);
}

// ---------- 3-phase scan ----------
__global__ void k_scan1() {
    __shared__ int warpsum[32];
    int tid = threadIdx.x, lane = tid & 31, wid = tid >> 5;
    int i = blockIdx.x * 1024 + tid;
    int v = (i < N_NODES) ? g_deg[i] : 0;
    int x = v;
#pragma unroll
    for (int off = 1; off < 32; off <<= 1) {
        int y = __shfl_up_sync(0xffffffffu, x, off);
        if (lane >= off) x += y;
    }
    if (lane == 31) warpsum[wid] = x;
    __syncthreads();
    if (wid == 0) {
        int w = warpsum[lane];
#pragma unroll
        for (int off = 1; off < 32; off <<= 1) {
            int y = __shfl_up_sync(0xffffffffu, w, off);
            if (lane >= off) w += y;
        }
        warpsum[lane] = w;
    }
    __syncthreads();
    int incl = x + (wid > 0 ? warpsum[wid - 1] : 0);
    if (i < N_NODES) {
        g_rowptr[i] = incl - v;
        g_dinv[i] = rsqrtf((float)(v + 1));
    }
    if (tid == 1023) g_bsum[blockIdx.x] = incl;
}

__global__ void k_scan2() {
    __shared__ int s[128];
    int t = threadIdx.x;
    s[t] = (t < NBLK_SCAN) ? g_bsum[t] : 0;
    __syncthreads();
    for (int off = 1; off < 128; off <<= 1) {
        int v = (t >= off) ? s[t - off] : 0;
        __syncthreads();
        s[t] += v;
        __syncthreads();
    }
    if (t < NBLK_SCAN) g_boff[t] = (t > 0) ? s[t - 1] : 0;
    if (t == 0) g_rowptr[N_NODES] = s[NBLK_SCAN - 1];
}

__global__ void k_scan3() {
    int i = blockIdx.x * 1024 + threadIdx.x;
    if (i >= N_NODES) return;
    int r = g_rowptr[i] + g_boff[blockIdx.x];
    g_rowptr[i] = r;
    g_cursor[i] = r;
}

// fill CSR: src read straight from edge_index
__global__ void k_fill(const void* ei) {
    int i = blockIdx.x * blockDim.x + threadIdx.x;   // 4 edges/thread
    int base = i * 4;
    if (base >= N_EDGES) return;
    int s0, s1, s2, s3;
    if (g_is32) {
        int4 sv = ((const int4*)ei)[i];
        s0 = sv.x; s1 = sv.y; s2 = sv.z; s3 = sv.w;
    } else {
        longlong2 a = ((const longlong2*)ei)[i * 2];
        longlong2 b = ((const longlong2*)ei)[i * 2 + 1];
        s0 = (int)a.x; s1 = (int)a.y; s2 = (int)b.x; s3 = (int)b.y;
    }
    int4 d = *(const int4*)&g_dst32[base];
    g_csrc[atomicAdd(&g_cursor[d.x], 1)] = s0;
    g_csrc[atomicAdd(&g_cursor[d.y], 1)] = s1;
    g_csrc[atomicAdd(&g_cursor[d.z], 1)] = s2;
    g_csrc[atomicAdd(&g_cursor[d.w], 1)] = s3;
}

// ================= fused encoder + GCN-weight GEMM (tf32) =================
// xw16[r,:] = fp16( dinv[r] * ( relu(x[r,:] @ W_enc + b_enc) @ W_gcn ) )
#define LDA 36
#define LDW 132

__global__ __launch_bounds__(256) void k_enc(
    const float* __restrict__ x, const float* __restrict__ W_enc,
    const float* __restrict__ b_enc, const float* __restrict__ W_gcn)
{
    extern __shared__ float pool[];
    float* xs = pool;             // 2 * 128*36 = 9216
    float* Ws = pool + 9216;      // 128*132   = 16896
    float* Hs = pool + 26112;     // 128*132   = 16896
    __shared__ float sbe[128];

    const int tid = threadIdx.x;
    const int wid = tid >> 5;
    const int wm = wid & 3, wn = wid >> 2;
    const int rowBase = blockIdx.x * 128;

    if (tid < 128) sbe[tid] = b_enc[tid];

#pragma unroll
    for (int i = 0; i < 16; i++) {
        int slot = tid + i * 256;
        int r = slot >> 5, c4 = (slot & 31) * 4;
        *(float4*)&Ws[r * LDW + c4] = *(const float4*)&W_enc[r * 128 + c4];
    }

    auto stageA = [&](int buf, int kt) {
        float* dst = xs + buf * (128 * LDA);
#pragma unroll
        for (int i = 0; i < 4; i++) {
            int slot = tid + i * 256;
            int r = slot >> 3, c4 = (slot & 7) * 4;
            int gr = rowBase + r;
            cp16(&dst[r * LDA + c4], &x[(size_t)gr * 128 + kt + c4], gr < N_NODES);
        }
        cp_commit();
    };

    wmma::fragment<wmma::accumulator, 16, 16, 8, float> acc[2][4];
#pragma unroll
    for (int mt = 0; mt < 2; mt++)
#pragma unroll
        for (int nt = 0; nt < 4; nt++) wmma::fill_fragment(acc[mt][nt], 0.f);

    stageA(0, 0);

    for (int c = 0; c < 4; c++) {
        if (c < 3) { stageA((c + 1) & 1, (c + 1) * 32); cp_wait<1>(); }
        else       cp_wait<0>();
        __syncthreads();
        float* cur = xs + (c & 1) * (128 * LDA);
#pragma unroll
        for (int ks = 0; ks < 4; ks++) {
            int k = ks * 8, kg = c * 32 + k;
            wmma::fragment<wmma::matrix_a, 16, 16, 8, wmma::precision::tf32, wmma::row_major> af[2];
            wmma::fragment<wmma::matrix_b, 16, 16, 8, wmma::precision::tf32, wmma::row_major> bf[4];
#pragma unroll
            for (int mt = 0; mt < 2; mt++) {
                wmma::load_matrix_sync(af[mt], &cur[(wm * 32 + mt * 16) * LDA + k], LDA);
#pragma unroll
                for (int e = 0; e < af[mt].num_elements; e++)
                    af[mt].x[e] = wmma::__float_to_tf32(af[mt].x[e]);
            }
#pragma unroll
            for (int nt = 0; nt < 4; nt++) {
                wmma::load_matrix_sync(bf[nt], &Ws[kg * LDW + wn * 64 + nt * 16], LDW);
#pragma unroll
                for (int e = 0; e < bf[nt].num_elements; e++)
                    bf[nt].x[e] = wmma::__float_to_tf32(bf[nt].x[e]);
            }
#pragma unroll
            for (int mt = 0; mt < 2; mt++)
#pragma unroll
                for (int nt = 0; nt < 4; nt++)
                    wmma::mma_sync(acc[mt][nt], af[mt], bf[nt], acc[mt][nt]);
        }
        __syncthreads();
    }

#pragma unroll
    for (int mt = 0; mt < 2; mt++)
#pragma unroll
        for (int nt = 0; nt < 4; nt++)
            wmma::store_matrix_sync(&Hs[(wm * 32 + mt * 16) * LDW + wn * 64 + nt * 16],
                                    acc[mt][nt], LDW, wmma::mem_row_major);
#pragma unroll
    for (int i = 0; i < 16; i++) {
        int slot = tid + i * 256;
        int r = slot >> 5, c4 = (slot & 31) * 4;
        *(float4*)&Ws[r * LDW + c4] = *(const float4*)&W_gcn[r * 128 + c4];
    }
    __syncthreads();

#pragma unroll
    for (int i = 0; i < 16; i++) {
        int slot = tid + i * 256;
        int r = slot >> 5, c4 = (slot & 31) * 4;
        float4 v = *(float4*)&Hs[r * LDW + c4];
        v.x = fmaxf(v.x + sbe[c4 + 0], 0.f);
        v.y = fmaxf(v.y + sbe[c4 + 1], 0.f);
        v.z = fmaxf(v.z + sbe[c4 + 2], 0.f);
        v.w = fmaxf(v.w + sbe[c4 + 3], 0.f);
        *(float4*)&Hs[r * LDW + c4] = v;
    }
    __syncthreads();

#pragma unroll
    for (int mt = 0; mt < 2; mt++)
#pragma unroll
        for (int nt = 0; nt < 4; nt++) wmma::fill_fragment(acc[mt][nt], 0.f);

#pragma unroll
    for (int ks = 0; ks < 16; ks++) {
        int k = ks * 8;
        wmma::fragment<wmma::matrix_a, 16, 16, 8, wmma::precision::tf32, wmma::row_major> af[2];
        wmma::fragment<wmma::matrix_b, 16, 16, 8, wmma::precision::tf32, wmma::row_major> bf[4];
#pragma unroll
        for (int mt = 0; mt < 2; mt++) {
            wmma::load_matrix_sync(af[mt], &Hs[(wm * 32 + mt * 16) * LDW + k], LDW);
#pragma unroll
            for (int e = 0; e < af[mt].num_elements; e++)
                af[mt].x[e] = wmma::__float_to_tf32(af[mt].x[e]);
        }
#pragma unroll
        for (int nt = 0; nt < 4; nt++) {
            wmma::load_matrix_sync(bf[nt], &Ws[k * LDW + wn * 64 + nt * 16], LDW);
#pragma unroll
            for (int e = 0; e < bf[nt].num_elements; e++)
                bf[nt].x[e] = wmma::__float_to_tf32(bf[nt].x[e]);
        }
#pragma unroll
        for (int mt = 0; mt < 2; mt++)
#pragma unroll
            for (int nt = 0; nt < 4; nt++)
                wmma::mma_sync(acc[mt][nt], af[mt], bf[nt], acc[mt][nt]);
    }
    __syncthreads();

#pragma unroll
    for (int mt = 0; mt < 2; mt++)
#pragma unroll
        for (int nt = 0; nt < 4; nt++)
            wmma::store_matrix_sync(&Hs[(wm * 32 + mt * 16) * LDW + wn * 64 + nt * 16],
                                    acc[mt][nt], LDW, wmma::mem_row_major);
    __syncthreads();

    // dinv scale + fp16 pack + store
#pragma unroll
    for (int i = 0; i < 16; i++) {
        int slot = tid + i * 256;
        int r = slot >> 5, c4 = (slot & 31) * 4;
        int gr = rowBase + r;
        float di = g_dinv[min(gr, N_NODES - 1)];
        float4 v = *(float4*)&Hs[r * LDW + c4];
        __half2 h0 = __floats2half2_rn(v.x * di, v.y * di);
        __half2 h1 = __floats2half2_rn(v.z * di, v.w * di);
        uint2 u;
        u.x = *(uint32_t*)&h0;
        u.y = *(uint32_t*)&h1;
        *(uint2*)&g_xw16[(size_t)gr * 128 + c4] = u;
    }
}

// ---------------- GCN aggregation: warp per node, fp16 gather ----------------
__device__ __forceinline__ void agg_row(float4& acc, int sj, int lane) {
    uint2 u = *(const uint2*)&g_xw16[(size_t)sj * 128 + lane * 4];
    float2 f0 = __half22float2(*(__half2*)&u.x);
    float2 f1 = __half22float2(*(__half2*)&u.y);
    acc.x += f0.x; acc.y += f0.y; acc.z += f1.x; acc.w += f1.y;
}

__global__ void k_agg(const float* __restrict__ b_gcn) {
    int gw = (blockIdx.x * blockDim.x + threadIdx.x) >> 5;
    int lane = threadIdx.x & 31;
    if (gw >= N_NODES) return;

    int beg = g_rowptr[gw];
    int end = g_rowptr[gw + 1];

    float4 acc = make_float4(0.f, 0.f, 0.f, 0.f);
    for (int base = beg; base < end; base += 32) {
        int e = base + lane;
        int s = (e < end) ? g_csrc[e] : 0;
        int cnt = min(32, end - base);
        if (cnt == 32) {
#pragma unroll
            for (int j = 0; j < 32; j++)
                agg_row(acc, __shfl_sync(0xffffffffu, s, j), lane);
        } else {
            for (int j = 0; j < cnt; j++)
                agg_row(acc, __shfl_sync(0xffffffffu, s, j), lane);
        }
    }

    float di = g_dinv[gw];
    float4 self = make_float4(0.f, 0.f, 0.f, 0.f);
    agg_row(self, gw, lane);
    float4 b = *(const float4*)&b_gcn[lane * 4];
    float4 o;
    o.x = fmaxf(fmaf(di, acc.x + self.x, b.x), 0.f);
    o.y = fmaxf(fmaf(di, acc.y + self.y, b.y), 0.f);
    o.z = fmaxf(fmaf(di, acc.z + self.z, b.z), 0.f);
    o.w = fmaxf(fmaf(di, acc.w + self.w, b.w), 0.f);
    __half2 ho0 = __floats2half2_rn(o.x, o.y);
    __half2 ho1 = __floats2half2_rn(o.z, o.w);
    uint2 u;
    u.x = *(uint32_t*)&ho0;
    u.y = *(uint32_t*)&ho1;
    *(uint2*)&g_h216[(size_t)gw * H + lane * 4] = u;
}

// ========== fused MLP head (fp16 wmma): out = relu(h2@W1+b1)@W2 + b2 ==========
#define LDA_H 40     // halves (80B rows)
#define LDB_H 264    // halves (528B rows)
#define LDT 264      // floats

__global__ __launch_bounds__(512) void k_w1out(
    const float* __restrict__ b1, const float* __restrict__ W2,
    const float* __restrict__ b2, float* __restrict__ out)
{
    extern __shared__ float pool[];
    __half* As = (__half*)pool;                    // 2 * 128*40  = 10240 h = 20480 B
    __half* Bs = (__half*)pool + 10240;            // 2 * 32*264  = 16896 h = 33792 B
    float*  Ts = pool;                             // alias: 128*264 f = 135168 B
    __shared__ float sW2[HQ * A_DIM];
    __shared__ float sb1[HQ];
    __shared__ float sb2[A_DIM];

    const int tid = threadIdx.x;
    const int wid = tid >> 5, lane = tid & 31;
    const int wm = wid & 3, wn = wid >> 2;
    const int rowBase = blockIdx.x * 128;

    for (int j = tid; j < HQ * A_DIM; j += 512) sW2[j] = W2[j];
    for (int j = tid; j < HQ; j += 512) sb1[j] = b1[j];
    if (tid < A_DIM) sb2[tid] = b2[tid];

    auto stage = [&](int buf, int kt) {
        __half* ad = As + buf * (128 * LDA_H);
        {   // A chunk: 128 rows x 32 halves = 512 x 16B, one per thread
            int r = tid >> 2, c8 = (tid & 3) * 8;
            cp16(&ad[r * LDA_H + c8], &g_h216[(size_t)(rowBase + r) * 128 + kt + c8], true);
        }
        __half* bd = Bs + buf * (32 * LDB_H);
#pragma unroll
        for (int i = 0; i < 2; i++) {   // B chunk: 32 rows x 256 halves = 1024 x 16B
            int slot = tid + i * 512;
            int r = slot >> 5, c8 = (slot & 31) * 8;
            cp16(&bd[r * LDB_H + c8], &g_W116[(size_t)(kt + r) * 256 + c8], true);
        }
        cp_commit();
    };

    wmma::fragment<wmma::accumulator, 16, 16, 16, float> acc[2][4];
#pragma unroll
    for (int mt = 0; mt < 2; mt++)
#pragma unroll
        for (int nt = 0; nt < 4; nt++) wmma::fill_fragment(acc[mt][nt], 0.f);

    stage(0, 0);
    for (int c = 0; c < 4; c++) {
        if (c < 3) { stage((c + 1) & 1, (c + 1) * 32); cp_wait<1>(); }
        else       cp_wait<0>();
        __syncthreads();
        __half* ac = As + (c & 1) * (128 * LDA_H);
        __half* bc = Bs + (c & 1) * (32 * LDB_H);
#pragma unroll
        for (int ks = 0; ks < 2; ks++) {
            int k = ks * 16;
            wmma::fragment<wmma::matrix_a, 16, 16, 16, __half, wmma::row_major> af[2];
            wmma::fragment<wmma::matrix_b, 16, 16, 16, __half, wmma::row_major> bf[4];
#pragma unroll
            for (int mt = 0; mt < 2; mt++)
                wmma::load_matrix_sync(af[mt], &ac[(wm * 32 + mt * 16) * LDA_H + k], LDA_H);
#pragma unroll
            for (int nt = 0; nt < 4; nt++)
                wmma::load_matrix_sync(bf[nt], &bc[k * LDB_H + wn * 64 + nt * 16], LDB_H);
#pragma unroll
            for (int mt = 0; mt < 2; mt++)
#pragma unroll
                for (int nt = 0; nt < 4; nt++)
                    wmma::mma_sync(acc[mt][nt], af[mt], bf[nt], acc[mt][nt]);
        }
        __syncthreads();
    }

#pragma unroll
    for (int mt = 0; mt < 2; mt++)
#pragma unroll
        for (int nt = 0; nt < 4; nt++)
            wmma::store_matrix_sync(&Ts[(wm * 32 + mt * 16) * LDT + wn * 64 + nt * 16],
                                    acc[mt][nt], LDT, wmma::mem_row_major);
    __syncthreads();

    int r0 = wid * 8;
#pragma unroll
    for (int rr = 0; rr < 8; rr++) {
        int r = r0 + rr;
        int gr = rowBase + r;
        float tv[8];
#pragma unroll
        for (int j = 0; j < 8; j++) {
            int cc = lane + 32 * j;
            tv[j] = fmaxf(Ts[r * LDT + cc] + sb1[cc], 0.f);
        }
        float o[A_DIM];
#pragma unroll
        for (int a = 0; a < A_DIM; a++) {
            float p = 0.f;
#pragma unroll
            for (int j = 0; j < 8; j++)
                p = fmaf(tv[j], sW2[(lane + 32 * j) * A_DIM + a], p);
#pragma unroll
            for (int off = 16; off; off >>= 1) p += __shfl_xor_sync(0xffffffffu, p, off);
            o[a] = p;
        }
        if (lane == 0 && gr < N_NODES) {
#pragma unroll
            for (int a = 0; a < A_DIM; a++)
                out[(size_t)gr * A_DIM + a] = o[a] + sb2[a];
        }
    }
}

// ---------------- launcher ----------------
extern "C" void kernel_launch(void* const* d_in, const int* in_sizes, int n_in,
                              void* d_out, int out_size) {
    const float* x     = (const float*)d_in[0];
    const void*  ei    = d_in[1];
    const float* W_enc = (const float*)d_in[2];
    const float* b_enc = (const float*)d_in[3];
    const float* W_gcn = (const float*)d_in[4];
    const float* b_gcn = (const float*)d_in[5];
    const float* W1    = (const float*)d_in[6];
    const float* b1    = (const float*)d_in[7];
    const float* W2    = (const float*)d_in[8];
    const float* b2    = (const float*)d_in[9];
    float* out = (float*)d_out;

    static cudaStream_t s2 = nullptr;
    static cudaEvent_t evF = nullptr, evScan = nullptr, evFill = nullptr;
    if (!s2) {   // created on the uncaptured correctness call; reused in capture
        cudaStreamCreateWithFlags(&s2, cudaStreamNonBlocking);
        cudaEventCreateWithFlags(&evF,    cudaEventDisableTiming);
        cudaEventCreateWithFlags(&evScan, cudaEventDisableTiming);
        cudaEventCreateWithFlags(&evFill, cudaEventDisableTiming);
        cudaFuncSetAttribute(k_enc,   cudaFuncAttributeMaxDynamicSharedMemorySize, 43008 * 4);
        cudaFuncSetAttribute(k_w1out, cudaFuncAttributeMaxDynamicSharedMemorySize, 33792 * 4);
    }

    // fork: CSR build + W1 conversion on s2
    cudaEventRecord(evF, 0);
    cudaStreamWaitEvent(s2, evF, 0);
    k_cvtW1<<<cdiv(HQ * H / 4, 256), 256, 0, s2>>>(W1);
    k_detect<<<1, 32, 0, s2>>>(ei);
    k_zero_deg<<<cdiv(N_NODES, 256), 256, 0, s2>>>();
    k_hist<<<cdiv(N_EDGES / 2, 256), 256, 0, s2>>>(ei);
    k_scan1<<<NBLK_SCAN, 1024, 0, s2>>>();
    k_scan2<<<1, 128, 0, s2>>>();
    k_scan3<<<NBLK_SCAN, 1024, 0, s2>>>();
    cudaEventRecord(evScan, s2);
    k_fill<<<cdiv(N_EDGES / 4, 256), 256, 0, s2>>>(ei);
    cudaEventRecord(evFill, s2);

    // main stream: encoder waits only for dinv (scan3); overlaps with k_fill
    cudaStreamWaitEvent(0, evScan, 0);
    k_enc<<<N_PAD / 128, 256, 43008 * 4>>>(x, W_enc, b_enc, W_gcn);

    // join: aggregation needs CSR (fill) + xw16
    cudaStreamWaitEvent(0, evFill, 0);
    k_agg<<<cdiv(N_NODES * 32, 256), 256>>>(b_gcn);
    k_w1out<<<N_PAD / 128, 512, 33792 * 4>>>(b1, W2, b2, out);
}

// round 6
// speedup vs baseline: 2.2191x; 1.0324x over previous
#include <cuda_runtime.h>
#include <cuda_fp16.h>
#include <mma.h>
#include <cstdint>

using namespace nvcuda;

#define N_NODES 100000
#define N_PAD   100096   // 782 * 128
#define N_EDGES 3200000
#define H 128
#define HQ 256
#define A_DIM 10
#define NBLK_SCAN 98

static inline int cdiv(int a, int b) { return (a + b - 1) / b; }

// ---------------- scratch ----------------
__device__ __half g_xw16[(size_t)N_PAD * H];  // fp16 relu(x@We+be)@Wg (UNscaled)
__device__ __half g_h216[(size_t)N_PAD * H];  // fp16 relu(gcn agg); pad rows stay 0
__device__ __half g_W116[HQ * H];             // fp16 W1 [128,256]
__device__ float  g_dinv[N_NODES];
__device__ int    g_deg[N_NODES];
__device__ int    g_rowptr[N_NODES + 1];
__device__ int    g_cursor[N_NODES];
__device__ int    g_csrc[N_EDGES];
__device__ int    g_dst32[N_EDGES];
__device__ int    g_is32;
__device__ int    g_bsum[NBLK_SCAN];
__device__ int    g_boff[NBLK_SCAN];

// ---------------- cp.async helpers ----------------
__device__ __forceinline__ void cp16(void* s, const void* g, bool p) {
    uint32_t sa = (uint32_t)__cvta_generic_to_shared(s);
    int sz = p ? 16 : 0;
    asm volatile("cp.async.cg.shared.global [%0], [%1], 16, %2;\n"
                 :: "r"(sa), "l"(g), "r"(sz));
}
__device__ __forceinline__ void cp_commit() {
    asm volatile("cp.async.commit_group;\n");
}
template <int NN>
__device__ __forceinline__ void cp_wait() {
    asm volatile("cp.async.wait_group %0;\n" :: "n"(NN));
}

// ---------------- W1 -> fp16 ----------------
__global__ void k_cvtW1(const float* __restrict__ W1) {
    int i = blockIdx.x * blockDim.x + threadIdx.x;
    int base = i * 4;
    if (base >= HQ * H) return;
    float4 v = *(const float4*)&W1[base];
    __half2 h0 = __floats2half2_rn(v.x, v.y);
    __half2 h1 = __floats2half2_rn(v.z, v.w);
    uint2 u;
    u.x = *(uint32_t*)&h0;
    u.y = *(uint32_t*)&h1;
    *(uint2*)&g_W116[base] = u;
}

// ---------------- edge dtype detect ----------------
__global__ void k_detect(const void* ei) {
    if (threadIdx.x == 0 && blockIdx.x == 0) {
        const long long* p = (const long long*)ei;
        int is32 = 0;
        for (int i = 0; i < 64; i++) {
            long long v = p[i];
            if (v < 0 || v >= (long long)N_NODES) { is32 = 1; break; }
        }
        g_is32 = is32;
    }
}

__global__ void k_zero_deg() {
    int i = blockIdx.x * blockDim.x + threadIdx.x;
    if (i < N_NODES) g_deg[i] = 0;
}

// histogram over dst half only; cache dst as int32
__global__ void k_hist(const void* ei) {
    int i = blockIdx.x * blockDim.x + threadIdx.x;   // 2 edges/thread
    int base = i * 2;
    if (base >= N_EDGES) return;
    int v0, v1;
    if (g_is32) {
        int2 p = ((const int2*)ei)[N_EDGES / 2 + i];
        v0 = p.x; v1 = p.y;
    } else {
        longlong2 p = ((const longlong2*)ei)[N_EDGES / 2 + i];
        v0 = (int)p.x; v1 = (int)p.y;
    }
    *(int2*)&g_dst32[base] = make_int2(v0, v1);
    atomicAdd(&g_deg[v0], 1);
    atomicAdd(&g_deg[v1], 1);
}

// ---------- 3-phase scan ----------
__global__ void k_scan1() {
    __shared__ int warpsum[32];
    int tid = threadIdx.x, lane = tid & 31, wid = tid >> 5;
    int i = blockIdx.x * 1024 + tid;
    int v = (i < N_NODES) ? g_deg[i] : 0;
    int x = v;
#pragma unroll
    for (int off = 1; off < 32; off <<= 1) {
        int y = __shfl_up_sync(0xffffffffu, x, off);
        if (lane >= off) x += y;
    }
    if (lane == 31) warpsum[wid] = x;
    __syncthreads();
    if (wid == 0) {
        int w = warpsum[lane];
#pragma unroll
        for (int off = 1; off < 32; off <<= 1) {
            int y = __shfl_up_sync(0xffffffffu, w, off);
            if (lane >= off) w += y;
        }
        warpsum[lane] = w;
    }
    __syncthreads();
    int incl = x + (wid > 0 ? warpsum[wid - 1] : 0);
    if (i < N_NODES) {
        g_rowptr[i] = incl - v;
        g_dinv[i] = rsqrtf((float)(v + 1));
    }
    if (tid == 1023) g_bsum[blockIdx.x] = incl;
}

__global__ void k_scan2() {
    __shared__ int s[128];
    int t = threadIdx.x;
    s[t] = (t < NBLK_SCAN) ? g_bsum[t] : 0;
    __syncthreads();
    for (int off = 1; off < 128; off <<= 1) {
        int v = (t >= off) ? s[t - off] : 0;
        __syncthreads();
        s[t] += v;
        __syncthreads();
    }
    if (t < NBLK_SCAN) g_boff[t] = (t > 0) ? s[t - 1] : 0;
    if (t == 0) g_rowptr[N_NODES] = s[NBLK_SCAN - 1];
}

__global__ void k_scan3() {
    int i = blockIdx.x * 1024 + threadIdx.x;
    if (i >= N_NODES) return;
    int r = g_rowptr[i] + g_boff[blockIdx.x];
    g_rowptr[i] = r;
    g_cursor[i] = r;
}

// fill CSR: src read straight from edge_index
__global__ void k_fill(const void* ei) {
    int i = blockIdx.x * blockDim.x + threadIdx.x;   // 4 edges/thread
    int base = i * 4;
    if (base >= N_EDGES) return;
    int s0, s1, s2, s3;
    if (g_is32) {
        int4 sv = ((const int4*)ei)[i];
        s0 = sv.x; s1 = sv.y; s2 = sv.z; s3 = sv.w;
    } else {
        longlong2 a = ((const longlong2*)ei)[i * 2];
        longlong2 b = ((const longlong2*)ei)[i * 2 + 1];
        s0 = (int)a.x; s1 = (int)a.y; s2 = (int)b.x; s3 = (int)b.y;
    }
    int4 d = *(const int4*)&g_dst32[base];
    g_csrc[atomicAdd(&g_cursor[d.x], 1)] = s0;
    g_csrc[atomicAdd(&g_cursor[d.y], 1)] = s1;
    g_csrc[atomicAdd(&g_cursor[d.z], 1)] = s2;
    g_csrc[atomicAdd(&g_cursor[d.w], 1)] = s3;
}

// ================= fused encoder + GCN-weight GEMM (tf32) =================
// xw16[r,:] = fp16( relu(x[r,:] @ W_enc + b_enc) @ W_gcn )   [no dinv scaling]
#define LDA 36
#define LDW 132

__global__ __launch_bounds__(256) void k_enc(
    const float* __restrict__ x, const float* __restrict__ W_enc,
    const float* __restrict__ b_enc, const float* __restrict__ W_gcn)
{
    extern __shared__ float pool[];
    float* xs = pool;             // 2 * 128*36 = 9216
    float* Ws = pool + 9216;      // 128*132   = 16896
    float* Hs = pool + 26112;     // 128*132   = 16896
    __shared__ float sbe[128];

    const int tid = threadIdx.x;
    const int wid = tid >> 5;
    const int wm = wid & 3, wn = wid >> 2;
    const int rowBase = blockIdx.x * 128;

    if (tid < 128) sbe[tid] = b_enc[tid];

#pragma unroll
    for (int i = 0; i < 16; i++) {
        int slot = tid + i * 256;
        int r = slot >> 5, c4 = (slot & 31) * 4;
        *(float4*)&Ws[r * LDW + c4] = *(const float4*)&W_enc[r * 128 + c4];
    }

    auto stageA = [&](int buf, int kt) {
        float* dst = xs + buf * (128 * LDA);
#pragma unroll
        for (int i = 0; i < 4; i++) {
            int slot = tid + i * 256;
            int r = slot >> 3, c4 = (slot & 7) * 4;
            int gr = rowBase + r;
            cp16(&dst[r * LDA + c4], &x[(size_t)gr * 128 + kt + c4], gr < N_NODES);
        }
        cp_commit();
    };

    wmma::fragment<wmma::accumulator, 16, 16, 8, float> acc[2][4];
#pragma unroll
    for (int mt = 0; mt < 2; mt++)
#pragma unroll
        for (int nt = 0; nt < 4; nt++) wmma::fill_fragment(acc[mt][nt], 0.f);

    stageA(0, 0);

    for (int c = 0; c < 4; c++) {
        if (c < 3) { stageA((c + 1) & 1, (c + 1) * 32); cp_wait<1>(); }
        else       cp_wait<0>();
        __syncthreads();
        float* cur = xs + (c & 1) * (128 * LDA);
#pragma unroll
        for (int ks = 0; ks < 4; ks++) {
            int k = ks * 8, kg = c * 32 + k;
            wmma::fragment<wmma::matrix_a, 16, 16, 8, wmma::precision::tf32, wmma::row_major> af[2];
            wmma::fragment<wmma::matrix_b, 16, 16, 8, wmma::precision::tf32, wmma::row_major> bf[4];
#pragma unroll
            for (int mt = 0; mt < 2; mt++) {
                wmma::load_matrix_sync(af[mt], &cur[(wm * 32 + mt * 16) * LDA + k], LDA);
#pragma unroll
                for (int e = 0; e < af[mt].num_elements; e++)
                    af[mt].x[e] = wmma::__float_to_tf32(af[mt].x[e]);
            }
#pragma unroll
            for (int nt = 0; nt < 4; nt++) {
                wmma::load_matrix_sync(bf[nt], &Ws[kg * LDW + wn * 64 + nt * 16], LDW);
#pragma unroll
                for (int e = 0; e < bf[nt].num_elements; e++)
                    bf[nt].x[e] = wmma::__float_to_tf32(bf[nt].x[e]);
            }
#pragma unroll
            for (int mt = 0; mt < 2; mt++)
#pragma unroll
                for (int nt = 0; nt < 4; nt++)
                    wmma::mma_sync(acc[mt][nt], af[mt], bf[nt], acc[mt][nt]);
        }
        __syncthreads();
    }

#pragma unroll
    for (int mt = 0; mt < 2; mt++)
#pragma unroll
        for (int nt = 0; nt < 4; nt++)
            wmma::store_matrix_sync(&Hs[(wm * 32 + mt * 16) * LDW + wn * 64 + nt * 16],
                                    acc[mt][nt], LDW, wmma::mem_row_major);
#pragma unroll
    for (int i = 0; i < 16; i++) {
        int slot = tid + i * 256;
        int r = slot >> 5, c4 = (slot & 31) * 4;
        *(float4*)&Ws[r * LDW + c4] = *(const float4*)&W_gcn[r * 128 + c4];
    }
    __syncthreads();

#pragma unroll
    for (int i = 0; i < 16; i++) {
        int slot = tid + i * 256;
        int r = slot >> 5, c4 = (slot & 31) * 4;
        float4 v = *(float4*)&Hs[r * LDW + c4];
        v.x = fmaxf(v.x + sbe[c4 + 0], 0.f);
        v.y = fmaxf(v.y + sbe[c4 + 1], 0.f);
        v.z = fmaxf(v.z + sbe[c4 + 2], 0.f);
        v.w = fmaxf(v.w + sbe[c4 + 3], 0.f);
        *(float4*)&Hs[r * LDW + c4] = v;
    }
    __syncthreads();

#pragma unroll
    for (int mt = 0; mt < 2; mt++)
#pragma unroll
        for (int nt = 0; nt < 4; nt++) wmma::fill_fragment(acc[mt][nt], 0.f);

#pragma unroll
    for (int ks = 0; ks < 16; ks++) {
        int k = ks * 8;
        wmma::fragment<wmma::matrix_a, 16, 16, 8, wmma::precision::tf32, wmma::row_major> af[2];
        wmma::fragment<wmma::matrix_b, 16, 16, 8, wmma::precision::tf32, wmma::row_major> bf[4];
#pragma unroll
        for (int mt = 0; mt < 2; mt++) {
            wmma::load_matrix_sync(af[mt], &Hs[(wm * 32 + mt * 16) * LDW + k], LDW);
#pragma unroll
            for (int e = 0; e < af[mt].num_elements; e++)
                af[mt].x[e] = wmma::__float_to_tf32(af[mt].x[e]);
        }
#pragma unroll
        for (int nt = 0; nt < 4; nt++) {
            wmma::load_matrix_sync(bf[nt], &Ws[k * LDW + wn * 64 + nt * 16], LDW);
#pragma unroll
            for (int e = 0; e < bf[nt].num_elements; e++)
                bf[nt].x[e] = wmma::__float_to_tf32(bf[nt].x[e]);
        }
#pragma unroll
        for (int mt = 0; mt < 2; mt++)
#pragma unroll
            for (int nt = 0; nt < 4; nt++)
                wmma::mma_sync(acc[mt][nt], af[mt], bf[nt], acc[mt][nt]);
    }
    __syncthreads();

#pragma unroll
    for (int mt = 0; mt < 2; mt++)
#pragma unroll
        for (int nt = 0; nt < 4; nt++)
            wmma::store_matrix_sync(&Hs[(wm * 32 + mt * 16) * LDW + wn * 64 + nt * 16],
                                    acc[mt][nt], LDW, wmma::mem_row_major);
    __syncthreads();

    // fp16 pack + store (no dinv)
#pragma unroll
    for (int i = 0; i < 16; i++) {
        int slot = tid + i * 256;
        int r = slot >> 5, c4 = (slot & 31) * 4;
        int gr = rowBase + r;
        float4 v = *(float4*)&Hs[r * LDW + c4];
        __half2 h0 = __floats2half2_rn(v.x, v.y);
        __half2 h1 = __floats2half2_rn(v.z, v.w);
        uint2 u;
        u.x = *(uint32_t*)&h0;
        u.y = *(uint32_t*)&h1;
        *(uint2*)&g_xw16[(size_t)gr * 128 + c4] = u;
    }
}

// ---------------- GCN aggregation: warp per node, fp16 gather, per-edge dinv ----------------
__device__ __forceinline__ void agg_row(float4& acc, int sj, int lane) {
    float c = g_dinv[sj];                 // warp-uniform broadcast load
    uint2 u = *(const uint2*)&g_xw16[(size_t)sj * 128 + lane * 4];
    float2 f0 = __half22float2(*(__half2*)&u.x);
    float2 f1 = __half22float2(*(__half2*)&u.y);
    acc.x = fmaf(c, f0.x, acc.x);
    acc.y = fmaf(c, f0.y, acc.y);
    acc.z = fmaf(c, f1.x, acc.z);
    acc.w = fmaf(c, f1.y, acc.w);
}

__global__ void k_agg(const float* __restrict__ b_gcn) {
    int gw = (blockIdx.x * blockDim.x + threadIdx.x) >> 5;
    int lane = threadIdx.x & 31;
    if (gw >= N_NODES) return;

    int beg = g_rowptr[gw];
    int end = g_rowptr[gw + 1];

    float4 acc = make_float4(0.f, 0.f, 0.f, 0.f);
    for (int base = beg; base < end; base += 32) {
        int e = base + lane;
        int s = (e < end) ? g_csrc[e] : 0;
        int cnt = min(32, end - base);
        if (cnt == 32) {
#pragma unroll
            for (int j = 0; j < 32; j++)
                agg_row(acc, __shfl_sync(0xffffffffu, s, j), lane);
        } else {
            for (int j = 0; j < cnt; j++)
                agg_row(acc, __shfl_sync(0xffffffffu, s, j), lane);
        }
    }

    float di = g_dinv[gw];
    // self term: di * xw[gw] added to acc, then whole thing scaled by di
    uint2 us = *(const uint2*)&g_xw16[(size_t)gw * 128 + lane * 4];
    float2 s0 = __half22float2(*(__half2*)&us.x);
    float2 s1 = __half22float2(*(__half2*)&us.y);
    acc.x = fmaf(di, s0.x, acc.x);
    acc.y = fmaf(di, s0.y, acc.y);
    acc.z = fmaf(di, s1.x, acc.z);
    acc.w = fmaf(di, s1.y, acc.w);

    float4 b = *(const float4*)&b_gcn[lane * 4];
    float4 o;
    o.x = fmaxf(fmaf(di, acc.x, b.x), 0.f);
    o.y = fmaxf(fmaf(di, acc.y, b.y), 0.f);
    o.z = fmaxf(fmaf(di, acc.z, b.z), 0.f);
    o.w = fmaxf(fmaf(di, acc.w, b.w), 0.f);
    __half2 ho0 = __floats2half2_rn(o.x, o.y);
    __half2 ho1 = __floats2half2_rn(o.z, o.w);
    uint2 u;
    u.x = *(uint32_t*)&ho0;
    u.y = *(uint32_t*)&ho1;
    *(uint2*)&g_h216[(size_t)gw * H + lane * 4] = u;
}

// ========== fused MLP head (fp16 wmma): out = relu(h2@W1+b1)@W2 + b2 ==========
#define LDA_H 40     // halves
#define LDB_H 264    // halves
#define LDT 264      // floats

__global__ __launch_bounds__(512) void k_w1out(
    const float* __restrict__ b1, const float* __restrict__ W2,
    const float* __restrict__ b2, float* __restrict__ out)
{
    extern __shared__ float pool[];
    __half* As = (__half*)pool;
    __half* Bs = (__half*)pool + 10240;
    float*  Ts = pool;
    __shared__ float sW2[HQ * A_DIM];
    __shared__ float sb1[HQ];
    __shared__ float sb2[A_DIM];

    const int tid = threadIdx.x;
    const int wid = tid >> 5, lane = tid & 31;
    const int wm = wid & 3, wn = wid >> 2;
    const int rowBase = blockIdx.x * 128;

    for (int j = tid; j < HQ * A_DIM; j += 512) sW2[j] = W2[j];
    for (int j = tid; j < HQ; j += 512) sb1[j] = b1[j];
    if (tid < A_DIM) sb2[tid] = b2[tid];

    auto stage = [&](int buf, int kt) {
        __half* ad = As + buf * (128 * LDA_H);
        {
            int r = tid >> 2, c8 = (tid & 3) * 8;
            cp16(&ad[r * LDA_H + c8], &g_h216[(size_t)(rowBase + r) * 128 + kt + c8], true);
        }
        __half* bd = Bs + buf * (32 * LDB_H);
#pragma unroll
        for (int i = 0; i < 2; i++) {
            int slot = tid + i * 512;
            int r = slot >> 5, c8 = (slot & 31) * 8;
            cp16(&bd[r * LDB_H + c8], &g_W116[(size_t)(kt + r) * 256 + c8], true);
        }
        cp_commit();
    };

    wmma::fragment<wmma::accumulator, 16, 16, 16, float> acc[2][4];
#pragma unroll
    for (int mt = 0; mt < 2; mt++)
#pragma unroll
        for (int nt = 0; nt < 4; nt++) wmma::fill_fragment(acc[mt][nt], 0.f);

    stage(0, 0);
    for (int c = 0; c < 4; c++) {
        if (c < 3) { stage((c + 1) & 1, (c + 1) * 32); cp_wait<1>(); }
        else       cp_wait<0>();
        __syncthreads();
        __half* ac = As + (c & 1) * (128 * LDA_H);
        __half* bc = Bs + (c & 1) * (32 * LDB_H);
#pragma unroll
        for (int ks = 0; ks < 2; ks++) {
            int k = ks * 16;
            wmma::fragment<wmma::matrix_a, 16, 16, 16, __half, wmma::row_major> af[2];
            wmma::fragment<wmma::matrix_b, 16, 16, 16, __half, wmma::row_major> bf[4];
#pragma unroll
            for (int mt = 0; mt < 2; mt++)
                wmma::load_matrix_sync(af[mt], &ac[(wm * 32 + mt * 16) * LDA_H + k], LDA_H);
#pragma unroll
            for (int nt = 0; nt < 4; nt++)
                wmma::load_matrix_sync(bf[nt], &bc[k * LDB_H + wn * 64 + nt * 16], LDB_H);
#pragma unroll
            for (int mt = 0; mt < 2; mt++)
#pragma unroll
                for (int nt = 0; nt < 4; nt++)
                    wmma::mma_sync(acc[mt][nt], af[mt], bf[nt], acc[mt][nt]);
        }
        __syncthreads();
    }

#pragma unroll
    for (int mt = 0; mt < 2; mt++)
#pragma unroll
        for (int nt = 0; nt < 4; nt++)
            wmma::store_matrix_sync(&Ts[(wm * 32 + mt * 16) * LDT + wn * 64 + nt * 16],
                                    acc[mt][nt], LDT, wmma::mem_row_major);
    __syncthreads();

    int r0 = wid * 8;
#pragma unroll
    for (int rr = 0; rr < 8; rr++) {
        int r = r0 + rr;
        int gr = rowBase + r;
        float tv[8];
#pragma unroll
        for (int j = 0; j < 8; j++) {
            int cc = lane + 32 * j;
            tv[j] = fmaxf(Ts[r * LDT + cc] + sb1[cc], 0.f);
        }
        float o[A_DIM];
#pragma unroll
        for (int a = 0; a < A_DIM; a++) {
            float p = 0.f;
#pragma unroll
            for (int j = 0; j < 8; j++)
                p = fmaf(tv[j], sW2[(lane + 32 * j) * A_DIM + a], p);
#pragma unroll
            for (int off = 16; off; off >>= 1) p += __shfl_xor_sync(0xffffffffu, p, off);
            o[a] = p;
        }
        if (lane == 0 && gr < N_NODES) {
#pragma unroll
            for (int a = 0; a < A_DIM; a++)
                out[(size_t)gr * A_DIM + a] = o[a] + sb2[a];
        }
    }
}

// ---------------- launcher ----------------
extern "C" void kernel_launch(void* const* d_in, const int* in_sizes, int n_in,
                              void* d_out, int out_size) {
    const float* x     = (const float*)d_in[0];
    const void*  ei    = d_in[1];
    const float* W_enc = (const float*)d_in[2];
    const float* b_enc = (const float*)d_in[3];
    const float* W_gcn = (const float*)d_in[4];
    const float* b_gcn = (const float*)d_in[5];
    const float* W1    = (const float*)d_in[6];
    const float* b1    = (const float*)d_in[7];
    const float* W2    = (const float*)d_in[8];
    const float* b2    = (const float*)d_in[9];
    float* out = (float*)d_out;

    static cudaStream_t s2 = nullptr;
    static cudaEvent_t evF = nullptr, evFill = nullptr;
    if (!s2) {   // created on the uncaptured correctness call; reused in capture
        cudaStreamCreateWithFlags(&s2, cudaStreamNonBlocking);
        cudaEventCreateWithFlags(&evF,    cudaEventDisableTiming);
        cudaEventCreateWithFlags(&evFill, cudaEventDisableTiming);
        cudaFuncSetAttribute(k_enc,   cudaFuncAttributeMaxDynamicSharedMemorySize, 43008 * 4);
        cudaFuncSetAttribute(k_w1out, cudaFuncAttributeMaxDynamicSharedMemorySize, 33792 * 4);
    }

    // fork: entire CSR build on s2 (independent of encoder now)
    cudaEventRecord(evF, 0);
    cudaStreamWaitEvent(s2, evF, 0);
    k_detect<<<1, 32, 0, s2>>>(ei);
    k_zero_deg<<<cdiv(N_NODES, 256), 256, 0, s2>>>();
    k_hist<<<cdiv(N_EDGES / 2, 256), 256, 0, s2>>>(ei);
    k_scan1<<<NBLK_SCAN, 1024, 0, s2>>>();
    k_scan2<<<1, 128, 0, s2>>>();
    k_scan3<<<NBLK_SCAN, 1024, 0, s2>>>();
    k_fill<<<cdiv(N_EDGES / 4, 256), 256, 0, s2>>>(ei);
    cudaEventRecord(evFill, s2);

    // main stream: W1 convert + encoder run immediately, fully overlapping CSR
    k_cvtW1<<<cdiv(HQ * H / 4, 256), 256>>>(W1);
    k_enc<<<N_PAD / 128, 256, 43008 * 4>>>(x, W_enc, b_enc, W_gcn);

    // join: aggregation needs CSR + dinv + xw16
    cudaStreamWaitEvent(0, evFill, 0);
    k_agg<<<cdiv(N_NODES * 32, 256), 256>>>(b_gcn);
    k_w1out<<<N_PAD / 128, 512, 33792 * 4>>>(b1, W2, b2, out);
}

// round 7
// speedup vs baseline: 2.4426x; 1.1007x over previous
#include <cuda_runtime.h>
#include <cuda_fp16.h>
#include <mma.h>
#include <cstdint>

using namespace nvcuda;

#define N_NODES 100000
#define N_PAD   100096   // 782 * 128
#define N_EDGES 3200000
#define H 128
#define HQ 256
#define A_DIM 10
#define NBLK_SCAN 98

static inline int cdiv(int a, int b) { return (a + b - 1) / b; }

// ---------------- scratch ----------------
__device__ __half g_xw16[(size_t)N_PAD * H];  // fp16 relu(x@We+be)@Wg (UNscaled)
__device__ __half g_h216[(size_t)N_PAD * H];  // fp16 relu(gcn agg); pad rows stay 0
__device__ __half g_W116[HQ * H];             // fp16 W1 [128,256]
__device__ __half g_Wg16[H * H];              // fp16 W_gcn [128,128]
__device__ float  g_dinv[N_NODES];
__device__ int    g_deg[N_NODES];
__device__ int    g_rowptr[N_NODES + 1];
__device__ int    g_cursor[N_NODES];
__device__ int    g_csrc[N_EDGES];
__device__ int    g_dst32[N_EDGES];
__device__ int    g_is32;
__device__ int    g_bsum[NBLK_SCAN];
__device__ int    g_boff[NBLK_SCAN];

// ---------------- cp.async helpers ----------------
__device__ __forceinline__ void cp16(void* s, const void* g, bool p) {
    uint32_t sa = (uint32_t)__cvta_generic_to_shared(s);
    int sz = p ? 16 : 0;
    asm volatile("cp.async.cg.shared.global [%0], [%1], 16, %2;\n"
                 :: "r"(sa), "l"(g), "r"(sz));
}
__device__ __forceinline__ void cp_commit() {
    asm volatile("cp.async.commit_group;\n");
}
template <int NN>
__device__ __forceinline__ void cp_wait() {
    asm volatile("cp.async.wait_group %0;\n" :: "n"(NN));
}

// ---------------- generic fp32 -> fp16 convert ----------------
__global__ void k_cvt16(const float* __restrict__ src, __half* __restrict__ dst, int n4) {
    int i = blockIdx.x * blockDim.x + threadIdx.x;
    if (i >= n4) return;
    float4 v = *(const float4*)&src[i * 4];
    __half2 h0 = __floats2half2_rn(v.x, v.y);
    __half2 h1 = __floats2half2_rn(v.z, v.w);
    uint2 u;
    u.x = *(uint32_t*)&h0;
    u.y = *(uint32_t*)&h1;
    *(uint2*)&dst[i * 4] = u;
}

// ---------------- edge dtype detect ----------------
__global__ void k_detect(const void* ei) {
    if (threadIdx.x == 0 && blockIdx.x == 0) {
        const long long* p = (const long long*)ei;
        int is32 = 0;
        for (int i = 0; i < 64; i++) {
            long long v = p[i];
            if (v < 0 || v >= (long long)N_NODES) { is32 = 1; break; }
        }
        g_is32 = is32;
    }
}

__global__ void k_zero_deg() {
    int i = blockIdx.x * blockDim.x + threadIdx.x;
    if (i < N_NODES) g_deg[i] = 0;
}

// histogram over dst half only; cache dst as int32
__global__ void k_hist(const void* ei) {
    int i = blockIdx.x * blockDim.x + threadIdx.x;   // 2 edges/thread
    int base = i * 2;
    if (base >= N_EDGES) return;
    int v0, v1;
    if (g_is32) {
        int2 p = ((const int2*)ei)[N_EDGES / 2 + i];
        v0 = p.x; v1 = p.y;
    } else {
        longlong2 p = ((const longlong2*)ei)[N_EDGES / 2 + i];
        v0 = (int)p.x; v1 = (int)p.y;
    }
    *(int2*)&g_dst32[base] = make_int2(v0, v1);
    atomicAdd(&g_deg[v0], 1);
    atomicAdd(&g_deg[v1], 1);
}

// ---------- 3-phase scan ----------
__global__ void k_scan1() {
    __shared__ int warpsum[32];
    int tid = threadIdx.x, lane = tid & 31, wid = tid >> 5;
    int i = blockIdx.x * 1024 + tid;
    int v = (i < N_NODES) ? g_deg[i] : 0;
    int x = v;
#pragma unroll
    for (int off = 1; off < 32; off <<= 1) {
        int y = __shfl_up_sync(0xffffffffu, x, off);
        if (lane >= off) x += y;
    }
    if (lane == 31) warpsum[wid] = x;
    __syncthreads();
    if (wid == 0) {
        int w = warpsum[lane];
#pragma unroll
        for (int off = 1; off < 32; off <<= 1) {
            int y = __shfl_up_sync(0xffffffffu, w, off);
            if (lane >= off) w += y;
        }
        warpsum[lane] = w;
    }
    __syncthreads();
    int incl = x + (wid > 0 ? warpsum[wid - 1] : 0);
    if (i < N_NODES) {
        g_rowptr[i] = incl - v;
        g_dinv[i] = rsqrtf((float)(v + 1));
    }
    if (tid == 1023) g_bsum[blockIdx.x] = incl;
}

__global__ void k_scan2() {
    __shared__ int s[128];
    int t = threadIdx.x;
    s[t] = (t < NBLK_SCAN) ? g_bsum[t] : 0;
    __syncthreads();
    for (int off = 1; off < 128; off <<= 1) {
        int v = (t >= off) ? s[t - off] : 0;
        __syncthreads();
        s[t] += v;
        __syncthreads();
    }
    if (t < NBLK_SCAN) g_boff[t] = (t > 0) ? s[t - 1] : 0;
    if (t == 0) g_rowptr[N_NODES] = s[NBLK_SCAN - 1];
}

__global__ void k_scan3() {
    int i = blockIdx.x * 1024 + threadIdx.x;
    if (i >= N_NODES) return;
    int r = g_rowptr[i] + g_boff[blockIdx.x];
    g_rowptr[i] = r;
    g_cursor[i] = r;
}

// fill CSR: src read straight from edge_index
__global__ void k_fill(const void* ei) {
    int i = blockIdx.x * blockDim.x + threadIdx.x;   // 4 edges/thread
    int base = i * 4;
    if (base >= N_EDGES) return;
    int s0, s1, s2, s3;
    if (g_is32) {
        int4 sv = ((const int4*)ei)[i];
        s0 = sv.x; s1 = sv.y; s2 = sv.z; s3 = sv.w;
    } else {
        longlong2 a = ((const longlong2*)ei)[i * 2];
        longlong2 b = ((const longlong2*)ei)[i * 2 + 1];
        s0 = (int)a.x; s1 = (int)a.y; s2 = (int)b.x; s3 = (int)b.y;
    }
    int4 d = *(const int4*)&g_dst32[base];
    g_csrc[atomicAdd(&g_cursor[d.x], 1)] = s0;
    g_csrc[atomicAdd(&g_cursor[d.y], 1)] = s1;
    g_csrc[atomicAdd(&g_cursor[d.z], 1)] = s2;
    g_csrc[atomicAdd(&g_cursor[d.w], 1)] = s3;
}

// ================= fused encoder + GCN-weight GEMM =================
// stage 1 (tf32): h1 = x @ W_enc ; stage 2 (fp16): xw = relu(h1+b) @ W_gcn
#define LDA 36        // floats, stage-1 A staging
#define LDW 132       // floats, W_enc / Hs
#define LDH 136       // halves, Hh / Wh (must be multiple of 8)

__global__ __launch_bounds__(256) void k_enc(
    const float* __restrict__ x, const float* __restrict__ W_enc,
    const float* __restrict__ b_enc)
{
    extern __shared__ float pool[];
    float*  xs = pool;                        // 2*128*36 f = 36864 B  [stage 1]
    float*  Ws = pool + 9216;                 // 128*132 f = 67584 B   [stage 1]
    float*  Hs = pool + 26112;                // 128*132 f = 67584 B   [both]
    __half* Hh = (__half*)pool;               // 128*136 h = 34816 B   [stage 2, aliases xs]
    __half* Wh = (__half*)(pool + 9216);      // 128*136 h = 34816 B   [stage 2, aliases Ws]
    __shared__ float sbe[128];

    const int tid = threadIdx.x;
    const int wid = tid >> 5;
    const int wm = wid & 3, wn = wid >> 2;
    const int rowBase = blockIdx.x * 128;

    if (tid < 128) sbe[tid] = b_enc[tid];

    // W_enc -> Ws (float)
#pragma unroll
    for (int i = 0; i < 16; i++) {
        int slot = tid + i * 256;
        int r = slot >> 5, c4 = (slot & 31) * 4;
        *(float4*)&Ws[r * LDW + c4] = *(const float4*)&W_enc[r * 128 + c4];
    }

    auto stageA = [&](int buf, int kt) {
        float* dst = xs + buf * (128 * LDA);
#pragma unroll
        for (int i = 0; i < 4; i++) {
            int slot = tid + i * 256;
            int r = slot >> 3, c4 = (slot & 7) * 4;
            int gr = rowBase + r;
            cp16(&dst[r * LDA + c4], &x[(size_t)gr * 128 + kt + c4], gr < N_NODES);
        }
        cp_commit();
    };

    // ---- stage 1: tf32, acc = x @ W_enc ----
    wmma::fragment<wmma::accumulator, 16, 16, 8, float> acc1[2][4];
#pragma unroll
    for (int mt = 0; mt < 2; mt++)
#pragma unroll
        for (int nt = 0; nt < 4; nt++) wmma::fill_fragment(acc1[mt][nt], 0.f);

    stageA(0, 0);
    for (int c = 0; c < 4; c++) {
        if (c < 3) { stageA((c + 1) & 1, (c + 1) * 32); cp_wait<1>(); }
        else       cp_wait<0>();
        __syncthreads();
        float* cur = xs + (c & 1) * (128 * LDA);
#pragma unroll
        for (int ks = 0; ks < 4; ks++) {
            int k = ks * 8, kg = c * 32 + k;
            wmma::fragment<wmma::matrix_a, 16, 16, 8, wmma::precision::tf32, wmma::row_major> af[2];
            wmma::fragment<wmma::matrix_b, 16, 16, 8, wmma::precision::tf32, wmma::row_major> bf[4];
#pragma unroll
            for (int mt = 0; mt < 2; mt++) {
                wmma::load_matrix_sync(af[mt], &cur[(wm * 32 + mt * 16) * LDA + k], LDA);
#pragma unroll
                for (int e = 0; e < af[mt].num_elements; e++)
                    af[mt].x[e] = wmma::__float_to_tf32(af[mt].x[e]);
            }
#pragma unroll
            for (int nt = 0; nt < 4; nt++) {
                wmma::load_matrix_sync(bf[nt], &Ws[kg * LDW + wn * 64 + nt * 16], LDW);
#pragma unroll
                for (int e = 0; e < bf[nt].num_elements; e++)
                    bf[nt].x[e] = wmma::__float_to_tf32(bf[nt].x[e]);
            }
#pragma unroll
            for (int mt = 0; mt < 2; mt++)
#pragma unroll
                for (int nt = 0; nt < 4; nt++)
                    wmma::mma_sync(acc1[mt][nt], af[mt], bf[nt], acc1[mt][nt]);
        }
        __syncthreads();   // also protects xs/Ws before stage-2 aliasing writes
    }

    // h1 tile -> Hs (float); W_gcn(fp16) -> Wh (aliases Ws, reads done)
#pragma unroll
    for (int mt = 0; mt < 2; mt++)
#pragma unroll
        for (int nt = 0; nt < 4; nt++)
            wmma::store_matrix_sync(&Hs[(wm * 32 + mt * 16) * LDW + wn * 64 + nt * 16],
                                    acc1[mt][nt], LDW, wmma::mem_row_major);
#pragma unroll
    for (int i = 0; i < 8; i++) {   // 128*128 halves = 2048 x 16B
        int slot = tid + i * 256;
        int r = slot >> 4, c8 = (slot & 15) * 8;
        *(uint4*)&Wh[r * LDH + c8] = *(const uint4*)&g_Wg16[r * 128 + c8];
    }
    __syncthreads();

    // bias + relu + fp16 pack: Hs -> Hh (aliases xs, reads done)
#pragma unroll
    for (int i = 0; i < 16; i++) {
        int slot = tid + i * 256;
        int r = slot >> 5, c4 = (slot & 31) * 4;
        float4 v = *(float4*)&Hs[r * LDW + c4];
        __half2 h0 = __floats2half2_rn(fmaxf(v.x + sbe[c4 + 0], 0.f),
                                       fmaxf(v.y + sbe[c4 + 1], 0.f));
        __half2 h1 = __floats2half2_rn(fmaxf(v.z + sbe[c4 + 2], 0.f),
                                       fmaxf(v.w + sbe[c4 + 3], 0.f));
        uint2 u;
        u.x = *(uint32_t*)&h0;
        u.y = *(uint32_t*)&h1;
        *(uint2*)&Hh[r * LDH + c4] = u;
    }
    __syncthreads();

    // ---- stage 2: fp16, acc = relu(h1) @ W_gcn ----
    wmma::fragment<wmma::accumulator, 16, 16, 16, float> acc2[2][4];
#pragma unroll
    for (int mt = 0; mt < 2; mt++)
#pragma unroll
        for (int nt = 0; nt < 4; nt++) wmma::fill_fragment(acc2[mt][nt], 0.f);

#pragma unroll
    for (int ks = 0; ks < 8; ks++) {
        int k = ks * 16;
        wmma::fragment<wmma::matrix_a, 16, 16, 16, __half, wmma::row_major> af[2];
        wmma::fragment<wmma::matrix_b, 16, 16, 16, __half, wmma::row_major> bf[4];
#pragma unroll
        for (int mt = 0; mt < 2; mt++)
            wmma::load_matrix_sync(af[mt], &Hh[(wm * 32 + mt * 16) * LDH + k], LDH);
#pragma unroll
        for (int nt = 0; nt < 4; nt++)
            wmma::load_matrix_sync(bf[nt], &Wh[k * LDH + wn * 64 + nt * 16], LDH);
#pragma unroll
        for (int mt = 0; mt < 2; mt++)
#pragma unroll
            for (int nt = 0; nt < 4; nt++)
                wmma::mma_sync(acc2[mt][nt], af[mt], bf[nt], acc2[mt][nt]);
    }
    __syncthreads();

#pragma unroll
    for (int mt = 0; mt < 2; mt++)
#pragma unroll
        for (int nt = 0; nt < 4; nt++)
            wmma::store_matrix_sync(&Hs[(wm * 32 + mt * 16) * LDW + wn * 64 + nt * 16],
                                    acc2[mt][nt], LDW, wmma::mem_row_major);
    __syncthreads();

    // fp16 pack + store
#pragma unroll
    for (int i = 0; i < 16; i++) {
        int slot = tid + i * 256;
        int r = slot >> 5, c4 = (slot & 31) * 4;
        int gr = rowBase + r;
        float4 v = *(float4*)&Hs[r * LDW + c4];
        __half2 h0 = __floats2half2_rn(v.x, v.y);
        __half2 h1 = __floats2half2_rn(v.z, v.w);
        uint2 u;
        u.x = *(uint32_t*)&h0;
        u.y = *(uint32_t*)&h1;
        *(uint2*)&g_xw16[(size_t)gr * 128 + c4] = u;
    }
}

// ------- GCN aggregation: 2 nodes/warp, 16 lanes x 16B per row -------
__device__ __forceinline__ void fma8(float* acc, float c, uint4 u) {
    __half2* h = (__half2*)&u;
#pragma unroll
    for (int q = 0; q < 4; q++) {
        float2 f = __half22float2(h[q]);
        acc[q * 2]     = fmaf(c, f.x, acc[q * 2]);
        acc[q * 2 + 1] = fmaf(c, f.y, acc[q * 2 + 1]);
    }
}

__global__ void k_agg(const float* __restrict__ b_gcn) {
    int warpId = (blockIdx.x * blockDim.x + threadIdx.x) >> 5;
    int lane = threadIdx.x & 31;
    int sub = lane >> 4;               // which node of the pair
    int l16 = lane & 15;
    unsigned hmask = sub ? 0xFFFF0000u : 0x0000FFFFu;
    int gw = warpId * 2 + sub;
    if (gw >= N_NODES) return;

    int beg = g_rowptr[gw];
    int end = g_rowptr[gw + 1];

    float acc[8];
#pragma unroll
    for (int q = 0; q < 8; q++) acc[q] = 0.f;

    const int colh = l16 * 8;          // 8 halves = 16B per lane

    for (int base = beg; base < end; base += 16) {
        int e = base + l16;
        int s = (e < end) ? g_csrc[e] : 0;
        int cnt = min(16, end - base);
        if (cnt == 16) {
#pragma unroll
            for (int j = 0; j < 16; j++) {
                int sj = __shfl_sync(hmask, s, sub * 16 + j);
                float c = g_dinv[sj];
                uint4 u = *(const uint4*)&g_xw16[(size_t)sj * 128 + colh];
                fma8(acc, c, u);
            }
        } else {
            for (int j = 0; j < cnt; j++) {
                int sj = __shfl_sync(hmask, s, sub * 16 + j);
                float c = g_dinv[sj];
                uint4 u = *(const uint4*)&g_xw16[(size_t)sj * 128 + colh];
                fma8(acc, c, u);
            }
        }
    }

    float di = g_dinv[gw];
    {   // self term
        uint4 u = *(const uint4*)&g_xw16[(size_t)gw * 128 + colh];
        fma8(acc, di, u);
    }

    float4 b0 = *(const float4*)&b_gcn[colh];
    float4 b1 = *(const float4*)&b_gcn[colh + 4];
    float bb[8] = {b0.x, b0.y, b0.z, b0.w, b1.x, b1.y, b1.z, b1.w};
    __half2 ho[4];
#pragma unroll
    for (int q = 0; q < 4; q++) {
        float ox = fmaxf(fmaf(di, acc[q * 2],     bb[q * 2]),     0.f);
        float oy = fmaxf(fmaf(di, acc[q * 2 + 1], bb[q * 2 + 1]), 0.f);
        ho[q] = __floats2half2_rn(ox, oy);
    }
    *(uint4*)&g_h216[(size_t)gw * 128 + colh] = *(uint4*)ho;
}

// ========== fused MLP head (fp16 wmma, single K stage) ==========
#define LDA2 136     // halves
#define LDB2 264     // halves
#define LDT 264      // floats

__global__ __launch_bounds__(512) void k_w1out(
    const float* __restrict__ b1, const float* __restrict__ W2,
    const float* __restrict__ b2, float* __restrict__ out)
{
    extern __shared__ float pool[];
    __half* As = (__half*)pool;                 // 128*136 h = 34816 B
    __half* Bs = (__half*)pool + 128 * LDA2;    // 128*264 h = 67584 B
    float*  Ts = pool;                          // alias: 128*264 f = 135168 B
    __shared__ float sW2[HQ * A_DIM];
    __shared__ float sb1[HQ];
    __shared__ float sb2[A_DIM];

    const int tid = threadIdx.x;
    const int wid = tid >> 5, lane = tid & 31;
    const int wm = wid & 3, wn = wid >> 2;
    const int rowBase = blockIdx.x * 128;

    for (int j = tid; j < HQ * A_DIM; j += 512) sW2[j] = W2[j];
    for (int j = tid; j < HQ; j += 512) sb1[j] = b1[j];
    if (tid < A_DIM) sb2[tid] = b2[tid];

    // single-shot staging: whole A (128x128 h) + whole B (128x256 h)
#pragma unroll
    for (int i = 0; i < 4; i++) {      // A: 2048 x 16B
        int slot = tid + i * 512;
        int r = slot >> 4, c8 = (slot & 15) * 8;
        cp16(&As[r * LDA2 + c8], &g_h216[(size_t)(rowBase + r) * 128 + c8], true);
    }
#pragma unroll
    for (int i = 0; i < 8; i++) {      // B: 4096 x 16B
        int slot = tid + i * 512;
        int r = slot >> 5, c8 = (slot & 31) * 8;
        cp16(&Bs[r * LDB2 + c8], &g_W116[(size_t)r * 256 + c8], true);
    }
    cp_commit();
    cp_wait<0>();
    __syncthreads();

    wmma::fragment<wmma::accumulator, 16, 16, 16, float> acc[2][4];
#pragma unroll
    for (int mt = 0; mt < 2; mt++)
#pragma unroll
        for (int nt = 0; nt < 4; nt++) wmma::fill_fragment(acc[mt][nt], 0.f);

#pragma unroll
    for (int ks = 0; ks < 8; ks++) {
        int k = ks * 16;
        wmma::fragment<wmma::matrix_a, 16, 16, 16, __half, wmma::row_major> af[2];
        wmma::fragment<wmma::matrix_b, 16, 16, 16, __half, wmma::row_major> bf[4];
#pragma unroll
        for (int mt = 0; mt < 2; mt++)
            wmma::load_matrix_sync(af[mt], &As[(wm * 32 + mt * 16) * LDA2 + k], LDA2);
#pragma unroll
        for (int nt = 0; nt < 4; nt++)
            wmma::load_matrix_sync(bf[nt], &Bs[k * LDB2 + wn * 64 + nt * 16], LDB2);
#pragma unroll
        for (int mt = 0; mt < 2; mt++)
#pragma unroll
            for (int nt = 0; nt < 4; nt++)
                wmma::mma_sync(acc[mt][nt], af[mt], bf[nt], acc[mt][nt]);
    }
    __syncthreads();   // As/Bs reads done before Ts alias write

#pragma unroll
    for (int mt = 0; mt < 2; mt++)
#pragma unroll
        for (int nt = 0; nt < 4; nt++)
            wmma::store_matrix_sync(&Ts[(wm * 32 + mt * 16) * LDT + wn * 64 + nt * 16],
                                    acc[mt][nt], LDT, wmma::mem_row_major);
    __syncthreads();

    int r0 = wid * 8;
#pragma unroll
    for (int rr = 0; rr < 8; rr++) {
        int r = r0 + rr;
        int gr = rowBase + r;
        float tv[8];
#pragma unroll
        for (int j = 0; j < 8; j++) {
            int cc = lane + 32 * j;
            tv[j] = fmaxf(Ts[r * LDT + cc] + sb1[cc], 0.f);
        }
        float o[A_DIM];
#pragma unroll
        for (int a = 0; a < A_DIM; a++) {
            float p = 0.f;
#pragma unroll
            for (int j = 0; j < 8; j++)
                p = fmaf(tv[j], sW2[(lane + 32 * j) * A_DIM + a], p);
#pragma unroll
            for (int off = 16; off; off >>= 1) p += __shfl_xor_sync(0xffffffffu, p, off);
            o[a] = p;
        }
        if (lane == 0 && gr < N_NODES) {
#pragma unroll
            for (int a = 0; a < A_DIM; a++)
                out[(size_t)gr * A_DIM + a] = o[a] + sb2[a];
        }
    }
}

// ---------------- launcher ----------------
extern "C" void kernel_launch(void* const* d_in, const int* in_sizes, int n_in,
                              void* d_out, int out_size) {
    const float* x     = (const float*)d_in[0];
    const void*  ei    = d_in[1];
    const float* W_enc = (const float*)d_in[2];
    const float* b_enc = (const float*)d_in[3];
    const float* W_gcn = (const float*)d_in[4];
    const float* b_gcn = (const float*)d_in[5];
    const float* W1    = (const float*)d_in[6];
    const float* b1    = (const float*)d_in[7];
    const float* W2    = (const float*)d_in[8];
    const float* b2    = (const float*)d_in[9];
    float* out = (float*)d_out;

    __half* w116 = nullptr; __half* wg16 = nullptr;
    cudaGetSymbolAddress((void**)&w116, g_W116);
    cudaGetSymbolAddress((void**)&wg16, g_Wg16);

    static cudaStream_t s2 = nullptr;
    static cudaEvent_t evF = nullptr, evFill = nullptr;
    if (!s2) {
        cudaStreamCreateWithFlags(&s2, cudaStreamNonBlocking);
        cudaEventCreateWithFlags(&evF,    cudaEventDisableTiming);
        cudaEventCreateWithFlags(&evFill, cudaEventDisableTiming);
        cudaFuncSetAttribute(k_enc,   cudaFuncAttributeMaxDynamicSharedMemorySize, 43008 * 4);
        cudaFuncSetAttribute(k_w1out, cudaFuncAttributeMaxDynamicSharedMemorySize, 33792 * 4);
    }

    // fork: CSR build on s2
    cudaEventRecord(evF, 0);
    cudaStreamWaitEvent(s2, evF, 0);
    k_detect<<<1, 32, 0, s2>>>(ei);
    k_zero_deg<<<cdiv(N_NODES, 256), 256, 0, s2>>>();
    k_hist<<<cdiv(N_EDGES / 2, 256), 256, 0, s2>>>(ei);
    k_scan1<<<NBLK_SCAN, 1024, 0, s2>>>();
    k_scan2<<<1, 128, 0, s2>>>();
    k_scan3<<<NBLK_SCAN, 1024, 0, s2>>>();
    k_fill<<<cdiv(N_EDGES / 4, 256), 256, 0, s2>>>(ei);
    cudaEventRecord(evFill, s2);

    // main: weight converts + encoder
    k_cvt16<<<cdiv(HQ * H / 4, 256), 256>>>(W1, w116, HQ * H / 4);
    k_cvt16<<<cdiv(H * H / 4, 256), 256>>>(W_gcn, wg16, H * H / 4);
    k_enc<<<N_PAD / 128, 256, 43008 * 4>>>(x, W_enc, b_enc);

    // join: aggregation needs CSR + dinv + xw16
    cudaStreamWaitEvent(0, evFill, 0);
    k_agg<<<cdiv(N_NODES / 2 * 32, 256), 256>>>(b_gcn);
    k_w1out<<<N_PAD / 128, 512, 33792 * 4>>>(b1, W2, b2, out);
}